// round 3
// baseline (speedup 1.0000x reference)
#include <cuda_runtime.h>
#include <cuda_bf16.h>
#include <mma.h>
#include <math.h>

using namespace nvcuda;

// Problem dims
#define NTOK   204800          // B*T*V = 64*128*25
#define NSEQ   8192            // B*T
#define SEQ    25
#define DMODEL 256
#define NHEAD  8
#define HDIM   32
#define DFFN   1024
#define D3     768

// ------------------------- scratch (device globals) -------------------------
__device__ __nv_bfloat16 g_yb  [(size_t)NTOK * DMODEL];   // LN1 output, bf16
__device__ __nv_bfloat16 g_qkv [(size_t)NTOK * D3];       // qkv, bf16
__device__ __nv_bfloat16 g_attn[(size_t)NTOK * DMODEL];   // attention out, bf16
__device__ float         g_x2  [(size_t)NTOK * DMODEL];   // residual after proj, fp32
__device__ __nv_bfloat16 g_y2  [(size_t)NTOK * DMODEL];   // LN2 output, bf16
__device__ __nv_bfloat16 g_hid [(size_t)NTOK * DFFN];     // ffn hidden, bf16
__device__ __nv_bfloat16 g_wqkv[DMODEL * D3];
__device__ __nv_bfloat16 g_wproj[DMODEL * DMODEL];
__device__ __nv_bfloat16 g_w1  [DMODEL * DFFN];
__device__ __nv_bfloat16 g_w2  [DFFN * DMODEL];

// ------------------------- helpers -------------------------
__device__ __forceinline__ void cp_async16(void* smem_dst, const void* gmem_src) {
    unsigned s = (unsigned)__cvta_generic_to_shared(smem_dst);
    asm volatile("cp.async.ca.shared.global [%0], [%1], 16;\n" :: "r"(s), "l"(gmem_src));
}
__device__ __forceinline__ void cp_async_commit() {
    asm volatile("cp.async.commit_group;\n");
}
__device__ __forceinline__ void cp_async_wait_all() {
    asm volatile("cp.async.wait_group 0;\n");
}

// ------------------------- weight fp32 -> bf16 -------------------------
__global__ void convert_w_kernel(const float* __restrict__ qkv_w,
                                 const float* __restrict__ proj_w,
                                 const float* __restrict__ w1,
                                 const float* __restrict__ w2) {
    int i0 = blockIdx.x * blockDim.x + threadIdx.x;
    int stride = gridDim.x * blockDim.x;
    for (int i = i0; i < DMODEL * D3; i += stride)     g_wqkv[i]  = __float2bfloat16(qkv_w[i]);
    for (int i = i0; i < DMODEL * DMODEL; i += stride) g_wproj[i] = __float2bfloat16(proj_w[i]);
    for (int i = i0; i < DMODEL * DFFN; i += stride)   g_w1[i]    = __float2bfloat16(w1[i]);
    for (int i = i0; i < DFFN * DMODEL; i += stride)   g_w2[i]    = __float2bfloat16(w2[i]);
}

// ------------------------- LayerNorm (warp per row, D=256) -------------------------
__global__ __launch_bounds__(256) void ln_kernel(const float* __restrict__ X,
                                                 const float* __restrict__ gam,
                                                 const float* __restrict__ bet,
                                                 __nv_bfloat16* __restrict__ Y) {
    int warp = (blockIdx.x * blockDim.x + threadIdx.x) >> 5;
    int lane = threadIdx.x & 31;
    if (warp >= NTOK) return;
    const float4* xp = (const float4*)(X + (size_t)warp * DMODEL);
    float4 v0 = xp[lane * 2];
    float4 v1 = xp[lane * 2 + 1];
    float s = v0.x + v0.y + v0.z + v0.w + v1.x + v1.y + v1.z + v1.w;
    #pragma unroll
    for (int o = 16; o > 0; o >>= 1) s += __shfl_xor_sync(0xffffffffu, s, o);
    float m = s * (1.0f / 256.0f);
    float d0x = v0.x - m, d0y = v0.y - m, d0z = v0.z - m, d0w = v0.w - m;
    float d1x = v1.x - m, d1y = v1.y - m, d1z = v1.z - m, d1w = v1.w - m;
    float vs = d0x*d0x + d0y*d0y + d0z*d0z + d0w*d0w + d1x*d1x + d1y*d1y + d1z*d1z + d1w*d1w;
    #pragma unroll
    for (int o = 16; o > 0; o >>= 1) vs += __shfl_xor_sync(0xffffffffu, vs, o);
    float rstd = rsqrtf(vs * (1.0f / 256.0f) + 1e-5f);
    const float4* gp = (const float4*)gam;
    const float4* bp = (const float4*)bet;
    float4 g0 = gp[lane * 2], g1 = gp[lane * 2 + 1];
    float4 b0 = bp[lane * 2], b1 = bp[lane * 2 + 1];
    float y[8];
    y[0] = d0x * rstd * g0.x + b0.x;  y[1] = d0y * rstd * g0.y + b0.y;
    y[2] = d0z * rstd * g0.z + b0.z;  y[3] = d0w * rstd * g0.w + b0.w;
    y[4] = d1x * rstd * g1.x + b1.x;  y[5] = d1y * rstd * g1.y + b1.y;
    y[6] = d1z * rstd * g1.z + b1.z;  y[7] = d1w * rstd * g1.w + b1.w;
    union { int4 i4; __nv_bfloat162 h2[4]; } u;
    u.h2[0] = __floats2bfloat162_rn(y[0], y[1]);
    u.h2[1] = __floats2bfloat162_rn(y[2], y[3]);
    u.h2[2] = __floats2bfloat162_rn(y[4], y[5]);
    u.h2[3] = __floats2bfloat162_rn(y[6], y[7]);
    *((int4*)(Y + (size_t)warp * DMODEL + lane * 8)) = u.i4;
}

// ------------------------- GEMM (bf16 WMMA, 128x128x32, cp.async double buffer) ----
// C[M,N] = A[M,K] @ B[K,N] + bias (+ epilogue). M = NTOK (multiple of 128),
// N, K multiples of 128/32. 256 threads = 8 warps, each warp computes 32x64.
enum { EPI_BF16 = 0, EPI_PROJ = 1, EPI_GELU = 2, EPI_OUT = 3 };

#define AS_STRIDE 40        // 32 + 8 pad (bf16 elems)
#define BS_STRIDE 136       // 128 + 8 pad
#define AS_BUF    (128 * AS_STRIDE)       // elems per buffer
#define BS_BUF    (32 * BS_STRIDE)
#define CS_STRIDE 132
#define GEMM_SMEM 69632     // max(load region 37888, epi 128*132*4=67584) rounded up

template <int EPI>
__global__ __launch_bounds__(256) void gemm_kernel(
    const __nv_bfloat16* __restrict__ A,
    const __nv_bfloat16* __restrict__ B,
    const float* __restrict__ bias,
    const float* __restrict__ res,
    void* __restrict__ out,
    int N, int K)
{
    extern __shared__ char smem_raw[];
    __nv_bfloat16* As = (__nv_bfloat16*)smem_raw;                 // [2][128][40]
    __nv_bfloat16* Bs = (__nv_bfloat16*)(smem_raw + 2 * AS_BUF * 2); // [2][32][136]
    float* Cs = (float*)smem_raw;                                 // [128][132]

    int t = threadIdx.x;
    int warp = t >> 5;
    int wm = warp >> 1;      // 0..3  (32-row slabs)
    int wn = warp & 1;       // 0..1  (64-col slabs)
    size_t m0 = (size_t)blockIdx.x * 128;
    int n0 = blockIdx.y * 128;

    wmma::fragment<wmma::accumulator, 16, 16, 16, float> c[2][4];
    #pragma unroll
    for (int i = 0; i < 2; i++)
        #pragma unroll
        for (int j = 0; j < 4; j++) wmma::fill_fragment(c[i][j], 0.0f);

    // prefetch tile 0
    {
        int idx = t;
        #pragma unroll
        for (int rep = 0; rep < 2; rep++, idx += 256) {
            int r = idx >> 2, ch = idx & 3;
            cp_async16(As + r * AS_STRIDE + ch * 8, A + (m0 + r) * K + ch * 8);
        }
        idx = t;
        #pragma unroll
        for (int rep = 0; rep < 2; rep++, idx += 256) {
            int r = idx >> 4, ch = idx & 15;
            cp_async16(Bs + r * BS_STRIDE + ch * 8, B + (size_t)r * N + n0 + ch * 8);
        }
        cp_async_commit();
    }

    int T = K >> 5;
    for (int tk = 0; tk < T; tk++) {
        int buf = tk & 1;
        cp_async_wait_all();
        __syncthreads();
        if (tk + 1 < T) {
            int kt = (tk + 1) << 5;
            int nb = buf ^ 1;
            int idx = t;
            #pragma unroll
            for (int rep = 0; rep < 2; rep++, idx += 256) {
                int r = idx >> 2, ch = idx & 3;
                cp_async16(As + nb * AS_BUF + r * AS_STRIDE + ch * 8,
                           A + (m0 + r) * K + kt + ch * 8);
            }
            idx = t;
            #pragma unroll
            for (int rep = 0; rep < 2; rep++, idx += 256) {
                int r = idx >> 4, ch = idx & 15;
                cp_async16(Bs + nb * BS_BUF + r * BS_STRIDE + ch * 8,
                           B + (size_t)(kt + r) * N + n0 + ch * 8);
            }
            cp_async_commit();
        }
        #pragma unroll
        for (int kk = 0; kk < 32; kk += 16) {
            wmma::fragment<wmma::matrix_a, 16, 16, 16, __nv_bfloat16, wmma::row_major> af[2];
            wmma::fragment<wmma::matrix_b, 16, 16, 16, __nv_bfloat16, wmma::row_major> bf_[4];
            #pragma unroll
            for (int i = 0; i < 2; i++)
                wmma::load_matrix_sync(af[i], As + buf * AS_BUF + (wm * 32 + i * 16) * AS_STRIDE + kk, AS_STRIDE);
            #pragma unroll
            for (int j = 0; j < 4; j++)
                wmma::load_matrix_sync(bf_[j], Bs + buf * BS_BUF + kk * BS_STRIDE + wn * 64 + j * 16, BS_STRIDE);
            #pragma unroll
            for (int i = 0; i < 2; i++)
                #pragma unroll
                for (int j = 0; j < 4; j++)
                    wmma::mma_sync(c[i][j], af[i], bf_[j], c[i][j]);
        }
        __syncthreads();
    }

    // epilogue: stage through smem (reuses load buffers)
    #pragma unroll
    for (int i = 0; i < 2; i++)
        #pragma unroll
        for (int j = 0; j < 4; j++)
            wmma::store_matrix_sync(Cs + (wm * 32 + i * 16) * CS_STRIDE + wn * 64 + j * 16,
                                    c[i][j], CS_STRIDE, wmma::mem_row_major);
    __syncthreads();

    int r = t >> 1;
    int half = (t & 1) * 64;
    size_t gr = m0 + r;
    #pragma unroll
    for (int cc = 0; cc < 8; cc++) {
        int col = half + cc * 8;
        const float4* cp4 = (const float4*)(Cs + r * CS_STRIDE + col);
        float4 a0 = cp4[0], a1 = cp4[1];
        const float4* bp4 = (const float4*)(bias + n0 + col);
        float4 bb0 = bp4[0], bb1 = bp4[1];
        float v[8];
        v[0] = a0.x + bb0.x; v[1] = a0.y + bb0.y; v[2] = a0.z + bb0.z; v[3] = a0.w + bb0.w;
        v[4] = a1.x + bb1.x; v[5] = a1.y + bb1.y; v[6] = a1.z + bb1.z; v[7] = a1.w + bb1.w;
        size_t oidx = gr * N + n0 + col;
        if (EPI == EPI_BF16 || EPI == EPI_GELU) {
            if (EPI == EPI_GELU) {
                #pragma unroll
                for (int e = 0; e < 8; e++)
                    v[e] = 0.5f * v[e] * (1.0f + erff(v[e] * 0.70710678118654752f));
            }
            union { int4 i4; __nv_bfloat162 h2[4]; } u;
            #pragma unroll
            for (int e = 0; e < 4; e++)
                u.h2[e] = __floats2bfloat162_rn(v[2 * e], v[2 * e + 1]);
            *((int4*)((__nv_bfloat16*)out + oidx)) = u.i4;
        } else {
            const float4* rp4 = (const float4*)(res + oidx);
            float4 r0 = rp4[0], r1 = rp4[1];
            float4 o0 = make_float4(v[0] + r0.x, v[1] + r0.y, v[2] + r0.z, v[3] + r0.w);
            float4 o1 = make_float4(v[4] + r1.x, v[5] + r1.y, v[6] + r1.z, v[7] + r1.w);
            float4* op4 = (float4*)((float*)out + oidx);
            op4[0] = o0;
            op4[1] = o1;
        }
    }
}

// ------------------------- Cosine attention (block per sequence, warp per head) ----
// q,k,v are 25x32 per head. Lane i (<25) owns row i. All global I/O vectorized int4.
__global__ __launch_bounds__(256) void attn_kernel(const float* __restrict__ logit_scale) {
    extern __shared__ float sm[];
    int n = blockIdx.x;
    int h = threadIdx.x >> 5;
    int lane = threadIdx.x & 31;

    float* kh = sm + h * (SEQ * HDIM);                    // [25][32]
    float* vh = sm + NHEAD * SEQ * HDIM + h * (SEQ * HDIM);

    float scale = expf(fminf(logit_scale[h], 4.6051701859880914f));  // log(100)

    float q[32];
    if (lane < SEQ) {
        // base of this row's qkv: q at +0, k at +256 bf16 (=32 int4), v at +512 (=64 int4)
        const int4* b4 = (const int4*)(g_qkv + (size_t)n * SEQ * D3 + (size_t)lane * D3 + h * HDIM);
        union { int4 i4; __nv_bfloat162 h2[4]; } uq[4], uk[4], uv[4];
        #pragma unroll
        for (int w = 0; w < 4; w++) {
            uq[w].i4 = b4[w];
            uk[w].i4 = b4[32 + w];
            uv[w].i4 = b4[64 + w];
        }
        float kv[32], vv[32];
        float qs = 0.0f, ks = 0.0f;
        #pragma unroll
        for (int w = 0; w < 4; w++) {
            #pragma unroll
            for (int e = 0; e < 4; e++) {
                float2 fq = __bfloat1622float2(uq[w].h2[e]);
                float2 fk = __bfloat1622float2(uk[w].h2[e]);
                float2 fv = __bfloat1622float2(uv[w].h2[e]);
                int d = w * 8 + e * 2;
                q[d] = fq.x;     q[d + 1] = fq.y;
                kv[d] = fk.x;    kv[d + 1] = fk.y;
                vv[d] = fv.x;    vv[d + 1] = fv.y;
                qs += fq.x * fq.x + fq.y * fq.y;
                ks += fk.x * fk.x + fk.y * fk.y;
            }
        }
        float qf = scale * 0.17677669529663687f / fmaxf(sqrtf(qs), 1e-12f);  // * 1/sqrt(32)
        float kf = 1.0f / fmaxf(sqrtf(ks), 1e-12f);
        float4* kp4 = (float4*)(kh + lane * 32);
        float4* vp4 = (float4*)(vh + lane * 32);
        #pragma unroll
        for (int w = 0; w < 8; w++) {
            int d = w * 4;
            q[d] *= qf; q[d+1] *= qf; q[d+2] *= qf; q[d+3] *= qf;
            kp4[w] = make_float4(kv[d] * kf, kv[d+1] * kf, kv[d+2] * kf, kv[d+3] * kf);
            vp4[w] = make_float4(vv[d], vv[d+1], vv[d+2], vv[d+3]);
        }
    }
    __syncwarp();

    if (lane < SEQ) {
        float lg[SEQ];
        float mx = -1e30f;
        #pragma unroll
        for (int j = 0; j < SEQ; j++) {
            const float4* kp4 = (const float4*)(kh + j * 32);
            float dot = 0.0f;
            #pragma unroll
            for (int tt = 0; tt < 8; tt++) {
                float4 kvv = kp4[tt];
                dot += q[tt * 4 + 0] * kvv.x + q[tt * 4 + 1] * kvv.y
                     + q[tt * 4 + 2] * kvv.z + q[tt * 4 + 3] * kvv.w;
            }
            lg[j] = dot;
            mx = fmaxf(mx, dot);
        }
        float ssum = 0.0f;
        #pragma unroll
        for (int j = 0; j < SEQ; j++) {
            lg[j] = expf(lg[j] - mx);
            ssum += lg[j];
        }
        float inv = 1.0f / ssum;

        float acc[32];
        #pragma unroll
        for (int d = 0; d < 32; d++) acc[d] = 0.0f;
        #pragma unroll
        for (int j = 0; j < SEQ; j++) {
            float a = lg[j];
            const float4* vp4 = (const float4*)(vh + j * 32);
            #pragma unroll
            for (int tt = 0; tt < 8; tt++) {
                float4 vvv = vp4[tt];
                acc[tt * 4 + 0] += a * vvv.x;
                acc[tt * 4 + 1] += a * vvv.y;
                acc[tt * 4 + 2] += a * vvv.z;
                acc[tt * 4 + 3] += a * vvv.w;
            }
        }
        union { int4 i4; __nv_bfloat162 h2[4]; } u;
        int4* op = (int4*)(g_attn + ((size_t)n * SEQ + lane) * DMODEL + h * HDIM);
        #pragma unroll
        for (int w = 0; w < 4; w++) {
            #pragma unroll
            for (int e = 0; e < 4; e++)
                u.h2[e] = __floats2bfloat162_rn(acc[w * 8 + 2 * e] * inv,
                                                acc[w * 8 + 2 * e + 1] * inv);
            op[w] = u.i4;
        }
    }
}

// ------------------------- launch -------------------------
extern "C" void kernel_launch(void* const* d_in, const int* in_sizes, int n_in,
                              void* d_out, int out_size) {
    const float* x           = (const float*)d_in[0];
    const float* ln1_g       = (const float*)d_in[1];
    const float* ln1_b       = (const float*)d_in[2];
    const float* qkv_w       = (const float*)d_in[3];
    const float* qkv_b       = (const float*)d_in[4];
    const float* proj_w      = (const float*)d_in[5];
    const float* proj_b      = (const float*)d_in[6];
    const float* logit_scale = (const float*)d_in[7];
    const float* ln2_g       = (const float*)d_in[8];
    const float* ln2_b       = (const float*)d_in[9];
    const float* w1          = (const float*)d_in[10];
    const float* b1          = (const float*)d_in[11];
    const float* w2          = (const float*)d_in[12];
    const float* b2          = (const float*)d_in[13];

    void *p_yb, *p_qkv, *p_attn, *p_x2, *p_y2, *p_hid, *p_wqkv, *p_wproj, *p_w1, *p_w2;
    cudaGetSymbolAddress(&p_yb, g_yb);
    cudaGetSymbolAddress(&p_qkv, g_qkv);
    cudaGetSymbolAddress(&p_attn, g_attn);
    cudaGetSymbolAddress(&p_x2, g_x2);
    cudaGetSymbolAddress(&p_y2, g_y2);
    cudaGetSymbolAddress(&p_hid, g_hid);
    cudaGetSymbolAddress(&p_wqkv, g_wqkv);
    cudaGetSymbolAddress(&p_wproj, g_wproj);
    cudaGetSymbolAddress(&p_w1, g_w1);
    cudaGetSymbolAddress(&p_w2, g_w2);

    const int ATTN_SMEM = 2 * NHEAD * SEQ * HDIM * (int)sizeof(float);  // 51200 B
    cudaFuncSetAttribute(attn_kernel, cudaFuncAttributeMaxDynamicSharedMemorySize, ATTN_SMEM);
    cudaFuncSetAttribute(gemm_kernel<EPI_BF16>, cudaFuncAttributeMaxDynamicSharedMemorySize, GEMM_SMEM);
    cudaFuncSetAttribute(gemm_kernel<EPI_PROJ>, cudaFuncAttributeMaxDynamicSharedMemorySize, GEMM_SMEM);
    cudaFuncSetAttribute(gemm_kernel<EPI_GELU>, cudaFuncAttributeMaxDynamicSharedMemorySize, GEMM_SMEM);
    cudaFuncSetAttribute(gemm_kernel<EPI_OUT>,  cudaFuncAttributeMaxDynamicSharedMemorySize, GEMM_SMEM);

    // 1) weights -> bf16
    convert_w_kernel<<<768, 256>>>(qkv_w, proj_w, w1, w2);
    // 2) LN1: x -> yb
    ln_kernel<<<NTOK / 8, 256>>>(x, ln1_g, ln1_b, (__nv_bfloat16*)p_yb);
    // 3) qkv GEMM: yb @ wqkv + b -> qkv (bf16)
    gemm_kernel<EPI_BF16><<<dim3(NTOK / 128, D3 / 128), 256, GEMM_SMEM>>>(
        (const __nv_bfloat16*)p_yb, (const __nv_bfloat16*)p_wqkv, qkv_b, nullptr, p_qkv, D3, DMODEL);
    // 4) attention
    attn_kernel<<<NSEQ, 256, ATTN_SMEM>>>(logit_scale);
    // 5) proj GEMM + residual -> x2 (fp32)
    gemm_kernel<EPI_PROJ><<<dim3(NTOK / 128, DMODEL / 128), 256, GEMM_SMEM>>>(
        (const __nv_bfloat16*)p_attn, (const __nv_bfloat16*)p_wproj, proj_b, x, p_x2, DMODEL, DMODEL);
    // 6) LN2: x2 -> y2
    ln_kernel<<<NTOK / 8, 256>>>((const float*)p_x2, ln2_g, ln2_b, (__nv_bfloat16*)p_y2);
    // 7) ffn1 GEMM + gelu -> hid (bf16)
    gemm_kernel<EPI_GELU><<<dim3(NTOK / 128, DFFN / 128), 256, GEMM_SMEM>>>(
        (const __nv_bfloat16*)p_y2, (const __nv_bfloat16*)p_w1, b1, nullptr, p_hid, DFFN, DMODEL);
    // 8) ffn2 GEMM + residual -> out (fp32)
    gemm_kernel<EPI_OUT><<<dim3(NTOK / 128, DMODEL / 128), 256, GEMM_SMEM>>>(
        (const __nv_bfloat16*)p_hid, (const __nv_bfloat16*)p_w2, b2, (const float*)p_x2, d_out, DMODEL, DFFN);
}

// round 11
// speedup vs baseline: 2.0489x; 2.0489x over previous
#include <cuda_runtime.h>
#include <cuda_bf16.h>
#include <cstdint>
#include <math.h>

// Problem dims
#define NTOK   204800          // B*T*V = 64*128*25
#define NSEQ   8192            // B*T
#define SEQ    25
#define DMODEL 256
#define NHEAD  8
#define HDIM   32
#define DFFN   1024
#define D3     768

// ------------------------- scratch (device globals) -------------------------
__device__ __nv_bfloat16 g_yb  [(size_t)NTOK * DMODEL];   // LN1 output, bf16
__device__ __nv_bfloat16 g_qkv [(size_t)NTOK * D3];       // qkv, bf16
__device__ __nv_bfloat16 g_attn[(size_t)NTOK * DMODEL];   // attention out, bf16
__device__ float         g_x2  [(size_t)NTOK * DMODEL];   // residual after proj, fp32
__device__ __nv_bfloat16 g_y2  [(size_t)NTOK * DMODEL];   // LN2 output, bf16
__device__ __nv_bfloat16 g_hid [(size_t)NTOK * DFFN];     // ffn hidden, bf16
// weights stored TRANSPOSED: [N, K] K-major (B operand, row.col mma)
__device__ __nv_bfloat16 g_wqkv [D3   * DMODEL];
__device__ __nv_bfloat16 g_wproj[DMODEL * DMODEL];
__device__ __nv_bfloat16 g_w1   [DFFN * DMODEL];
__device__ __nv_bfloat16 g_w2   [DMODEL * DFFN];

// ------------------------- ptx helpers -------------------------
__device__ __forceinline__ void cp_async16(uint32_t smem_dst, const void* gmem_src) {
    asm volatile("cp.async.cg.shared.global [%0], [%1], 16;\n" :: "r"(smem_dst), "l"(gmem_src));
}
__device__ __forceinline__ void ldmatrix_x4(uint32_t& r0, uint32_t& r1, uint32_t& r2,
                                            uint32_t& r3, uint32_t addr) {
    asm volatile("ldmatrix.sync.aligned.m8n8.x4.shared.b16 {%0,%1,%2,%3}, [%4];"
                 : "=r"(r0), "=r"(r1), "=r"(r2), "=r"(r3) : "r"(addr));
}
__device__ __forceinline__ void mma16816(float& d0, float& d1, float& d2, float& d3,
                                         uint32_t a0, uint32_t a1, uint32_t a2, uint32_t a3,
                                         uint32_t b0, uint32_t b1) {
    asm volatile(
        "mma.sync.aligned.m16n8k16.row.col.f32.bf16.bf16.f32 "
        "{%0,%1,%2,%3}, {%4,%5,%6,%7}, {%8,%9}, {%0,%1,%2,%3};"
        : "+f"(d0), "+f"(d1), "+f"(d2), "+f"(d3)
        : "r"(a0), "r"(a1), "r"(a2), "r"(a3), "r"(b0), "r"(b1));
}

// ------------------------- weight fp32 -> bf16 (TRANSPOSED to [N,K]) -----------
__global__ void convert_w_kernel(const float* __restrict__ qkv_w,
                                 const float* __restrict__ proj_w,
                                 const float* __restrict__ w1,
                                 const float* __restrict__ w2) {
    int i0 = blockIdx.x * blockDim.x + threadIdx.x;
    int stride = gridDim.x * blockDim.x;
    for (int i = i0; i < D3 * DMODEL; i += stride) {
        int n = i >> 8, k = i & 255;
        g_wqkv[i] = __float2bfloat16(qkv_w[k * D3 + n]);
    }
    for (int i = i0; i < DMODEL * DMODEL; i += stride) {
        int n = i >> 8, k = i & 255;
        g_wproj[i] = __float2bfloat16(proj_w[k * DMODEL + n]);
    }
    for (int i = i0; i < DFFN * DMODEL; i += stride) {
        int n = i >> 8, k = i & 255;
        g_w1[i] = __float2bfloat16(w1[k * DFFN + n]);
    }
    for (int i = i0; i < DMODEL * DFFN; i += stride) {
        int n = i >> 10, k = i & 1023;
        g_w2[i] = __float2bfloat16(w2[k * DMODEL + n]);
    }
}

// ------------------------- LayerNorm (warp per row, D=256) -------------------------
__global__ __launch_bounds__(256) void ln_kernel(const float* __restrict__ X,
                                                 const float* __restrict__ gam,
                                                 const float* __restrict__ bet,
                                                 __nv_bfloat16* __restrict__ Y) {
    int warp = (blockIdx.x * blockDim.x + threadIdx.x) >> 5;
    int lane = threadIdx.x & 31;
    if (warp >= NTOK) return;
    const float4* xp = (const float4*)(X + (size_t)warp * DMODEL);
    float4 v0 = xp[lane * 2];
    float4 v1 = xp[lane * 2 + 1];
    float s = v0.x + v0.y + v0.z + v0.w + v1.x + v1.y + v1.z + v1.w;
    #pragma unroll
    for (int o = 16; o > 0; o >>= 1) s += __shfl_xor_sync(0xffffffffu, s, o);
    float m = s * (1.0f / 256.0f);
    float d0x = v0.x - m, d0y = v0.y - m, d0z = v0.z - m, d0w = v0.w - m;
    float d1x = v1.x - m, d1y = v1.y - m, d1z = v1.z - m, d1w = v1.w - m;
    float vs = d0x*d0x + d0y*d0y + d0z*d0z + d0w*d0w + d1x*d1x + d1y*d1y + d1z*d1z + d1w*d1w;
    #pragma unroll
    for (int o = 16; o > 0; o >>= 1) vs += __shfl_xor_sync(0xffffffffu, vs, o);
    float rstd = rsqrtf(vs * (1.0f / 256.0f) + 1e-5f);
    const float4* gp = (const float4*)gam;
    const float4* bp = (const float4*)bet;
    float4 g0 = gp[lane * 2], g1 = gp[lane * 2 + 1];
    float4 b0 = bp[lane * 2], b1 = bp[lane * 2 + 1];
    float y[8];
    y[0] = d0x * rstd * g0.x + b0.x;  y[1] = d0y * rstd * g0.y + b0.y;
    y[2] = d0z * rstd * g0.z + b0.z;  y[3] = d0w * rstd * g0.w + b0.w;
    y[4] = d1x * rstd * g1.x + b1.x;  y[5] = d1y * rstd * g1.y + b1.y;
    y[6] = d1z * rstd * g1.z + b1.z;  y[7] = d1w * rstd * g1.w + b1.w;
    union { int4 i4; __nv_bfloat162 h2[4]; } u;
    u.h2[0] = __floats2bfloat162_rn(y[0], y[1]);
    u.h2[1] = __floats2bfloat162_rn(y[2], y[3]);
    u.h2[2] = __floats2bfloat162_rn(y[4], y[5]);
    u.h2[3] = __floats2bfloat162_rn(y[6], y[7]);
    *((int4*)(Y + (size_t)warp * DMODEL + lane * 8)) = u.i4;
}

// ------------------------- mma.sync GEMM -------------------------
// C[M,N] = A[M,K] @ Bw[N,K]^T + bias (+ epilogue).
// 128x128 CTA tile, BK=32, 3-stage cp.async pipeline, 8 warps, warp tile 32x64.
enum { EPI_BF16 = 0, EPI_PROJ = 1, EPI_GELU = 2, EPI_OUT = 3 };

#define ROWB   80                    // padded row pitch in bytes (32 bf16 + 8 pad)
#define STAGE_A 10240                // 128 * 80
#define STAGE  20480                 // A + B per stage
#define GSMEM  61440                 // 3 stages

template <int EPI>
__global__ __launch_bounds__(256) void mm_gemm(
    const __nv_bfloat16* __restrict__ A,
    const __nv_bfloat16* __restrict__ Bw,
    const float* __restrict__ bias,
    const float* __restrict__ res,
    void* __restrict__ out, int N, int K)
{
    extern __shared__ __align__(128) char smem[];
    const uint32_t sb = (uint32_t)__cvta_generic_to_shared(smem);
    const int t = threadIdx.x, wid = t >> 5, lane = t & 31;
    const int wm = wid & 3;          // 0..3 -> 32-row slab
    const int wn = wid >> 2;         // 0..1 -> 64-col slab
    const size_t m0 = (size_t)blockIdx.y * 128;
    const int n0 = blockIdx.x * 128;
    const int C = K >> 5;            // BK=32 chunks

    // load one K-chunk into stage s
    auto load_chunk = [&](int c, int s) {
        const uint32_t base = sb + (uint32_t)s * STAGE;
        const int k0 = c << 5;
        #pragma unroll
        for (int i = 0; i < 2; i++) {
            int idx = i * 256 + t;
            int r = idx >> 2, cc = idx & 3;
            cp_async16(base + (uint32_t)(r * ROWB + cc * 16),
                       A + (m0 + r) * K + k0 + cc * 8);
        }
        #pragma unroll
        for (int i = 0; i < 2; i++) {
            int idx = i * 256 + t;
            int r = idx >> 2, cc = idx & 3;
            cp_async16(base + STAGE_A + (uint32_t)(r * ROWB + cc * 16),
                       Bw + (size_t)(n0 + r) * K + k0 + cc * 8);
        }
        asm volatile("cp.async.commit_group;");
    };

    float acc[2][8][4];
    #pragma unroll
    for (int i = 0; i < 2; i++)
        #pragma unroll
        for (int j = 0; j < 8; j++)
            #pragma unroll
            for (int e = 0; e < 4; e++) acc[i][j][e] = 0.0f;

    load_chunk(0, 0);
    load_chunk(1, 1);

    for (int c = 0; c < C; c++) {
        if (c < C - 1) { asm volatile("cp.async.wait_group 1;"); }
        else           { asm volatile("cp.async.wait_group 0;"); }
        __syncthreads();
        if (c + 2 < C) load_chunk(c + 2, (c + 2) % 3);

        const uint32_t aBase = sb + (uint32_t)(c % 3) * STAGE;
        const uint32_t bBase = aBase + STAGE_A;
        // B via direct LDS.32 (conflict-free: banks n*20+q all distinct mod 32)
        const uint32_t* Bp = (const uint32_t*)(smem + (size_t)(c % 3) * STAGE + STAGE_A);

        #pragma unroll
        for (int ks = 0; ks < 2; ks++) {
            uint32_t a[2][4];
            #pragma unroll
            for (int i = 0; i < 2; i++) {
                uint32_t addr = aBase
                    + (uint32_t)((wm * 32 + i * 16 + (lane & 15)) * ROWB
                                 + ks * 32 + (lane >> 4) * 16);
                ldmatrix_x4(a[i][0], a[i][1], a[i][2], a[i][3], addr);
            }
            #pragma unroll
            for (int j = 0; j < 8; j++) {
                int n = wn * 64 + j * 8 + (lane >> 2);
                int kq = ks * 8 + (lane & 3);      // uint32 index within row
                uint32_t b0 = Bp[n * 20 + kq];
                uint32_t b1 = Bp[n * 20 + kq + 4];
                #pragma unroll
                for (int i = 0; i < 2; i++)
                    mma16816(acc[i][j][0], acc[i][j][1], acc[i][j][2], acc[i][j][3],
                             a[i][0], a[i][1], a[i][2], a[i][3], b0, b1);
            }
        }
        __syncthreads();
    }

    // epilogue straight from fragments
    const int qrow = lane >> 2;
    const int qcol = (lane & 3) * 2;
    #pragma unroll
    for (int i = 0; i < 2; i++) {
        #pragma unroll
        for (int j = 0; j < 8; j++) {
            int col = n0 + wn * 64 + j * 8 + qcol;
            float2 bb = *(const float2*)(bias + col);
            #pragma unroll
            for (int h = 0; h < 2; h++) {
                size_t row = m0 + wm * 32 + i * 16 + qrow + h * 8;
                float v0 = acc[i][j][2 * h + 0] + bb.x;
                float v1 = acc[i][j][2 * h + 1] + bb.y;
                size_t o = row * (size_t)N + col;
                if (EPI == EPI_BF16) {
                    *(__nv_bfloat162*)((__nv_bfloat16*)out + o) = __floats2bfloat162_rn(v0, v1);
                } else if (EPI == EPI_GELU) {
                    v0 = 0.5f * v0 * (1.0f + erff(v0 * 0.70710678118654752f));
                    v1 = 0.5f * v1 * (1.0f + erff(v1 * 0.70710678118654752f));
                    *(__nv_bfloat162*)((__nv_bfloat16*)out + o) = __floats2bfloat162_rn(v0, v1);
                } else {
                    float2 rr = *(const float2*)(res + o);
                    float2 ov = make_float2(v0 + rr.x, v1 + rr.y);
                    *(float2*)((float*)out + o) = ov;
                }
            }
        }
    }
}

// ------------------------- Cosine attention (block per sequence, warp per head) ----
__global__ __launch_bounds__(256) void attn_kernel(const float* __restrict__ logit_scale) {
    extern __shared__ float sm[];
    int n = blockIdx.x;
    int h = threadIdx.x >> 5;
    int lane = threadIdx.x & 31;

    float* kh = sm + h * (SEQ * HDIM);
    float* vh = sm + NHEAD * SEQ * HDIM + h * (SEQ * HDIM);

    float scale = expf(fminf(logit_scale[h], 4.6051701859880914f));  // log(100)

    float q[32];
    if (lane < SEQ) {
        const int4* b4 = (const int4*)(g_qkv + (size_t)n * SEQ * D3 + (size_t)lane * D3 + h * HDIM);
        union { int4 i4; __nv_bfloat162 h2[4]; } uq[4], uk[4], uv[4];
        #pragma unroll
        for (int w = 0; w < 4; w++) {
            uq[w].i4 = b4[w];
            uk[w].i4 = b4[32 + w];
            uv[w].i4 = b4[64 + w];
        }
        float kv[32], vv[32];
        float qs = 0.0f, ks = 0.0f;
        #pragma unroll
        for (int w = 0; w < 4; w++) {
            #pragma unroll
            for (int e = 0; e < 4; e++) {
                float2 fq = __bfloat1622float2(uq[w].h2[e]);
                float2 fk = __bfloat1622float2(uk[w].h2[e]);
                float2 fv = __bfloat1622float2(uv[w].h2[e]);
                int d = w * 8 + e * 2;
                q[d] = fq.x;     q[d + 1] = fq.y;
                kv[d] = fk.x;    kv[d + 1] = fk.y;
                vv[d] = fv.x;    vv[d + 1] = fv.y;
                qs += fq.x * fq.x + fq.y * fq.y;
                ks += fk.x * fk.x + fk.y * fk.y;
            }
        }
        float qf = scale * 0.17677669529663687f / fmaxf(sqrtf(qs), 1e-12f);
        float kf = 1.0f / fmaxf(sqrtf(ks), 1e-12f);
        float4* kp4 = (float4*)(kh + lane * 32);
        float4* vp4 = (float4*)(vh + lane * 32);
        #pragma unroll
        for (int w = 0; w < 8; w++) {
            int d = w * 4;
            q[d] *= qf; q[d+1] *= qf; q[d+2] *= qf; q[d+3] *= qf;
            kp4[w] = make_float4(kv[d] * kf, kv[d+1] * kf, kv[d+2] * kf, kv[d+3] * kf);
            vp4[w] = make_float4(vv[d], vv[d+1], vv[d+2], vv[d+3]);
        }
    }
    __syncwarp();

    if (lane < SEQ) {
        float lg[SEQ];
        float mx = -1e30f;
        #pragma unroll
        for (int j = 0; j < SEQ; j++) {
            const float4* kp4 = (const float4*)(kh + j * 32);
            float dot = 0.0f;
            #pragma unroll
            for (int tt = 0; tt < 8; tt++) {
                float4 kvv = kp4[tt];
                dot += q[tt * 4 + 0] * kvv.x + q[tt * 4 + 1] * kvv.y
                     + q[tt * 4 + 2] * kvv.z + q[tt * 4 + 3] * kvv.w;
            }
            lg[j] = dot;
            mx = fmaxf(mx, dot);
        }
        float ssum = 0.0f;
        #pragma unroll
        for (int j = 0; j < SEQ; j++) {
            lg[j] = expf(lg[j] - mx);
            ssum += lg[j];
        }
        float inv = 1.0f / ssum;

        float acc[32];
        #pragma unroll
        for (int d = 0; d < 32; d++) acc[d] = 0.0f;
        #pragma unroll
        for (int j = 0; j < SEQ; j++) {
            float a = lg[j];
            const float4* vp4 = (const float4*)(vh + j * 32);
            #pragma unroll
            for (int tt = 0; tt < 8; tt++) {
                float4 vvv = vp4[tt];
                acc[tt * 4 + 0] += a * vvv.x;
                acc[tt * 4 + 1] += a * vvv.y;
                acc[tt * 4 + 2] += a * vvv.z;
                acc[tt * 4 + 3] += a * vvv.w;
            }
        }
        union { int4 i4; __nv_bfloat162 h2[4]; } u;
        int4* op = (int4*)(g_attn + ((size_t)n * SEQ + lane) * DMODEL + h * HDIM);
        #pragma unroll
        for (int w = 0; w < 4; w++) {
            #pragma unroll
            for (int e = 0; e < 4; e++)
                u.h2[e] = __floats2bfloat162_rn(acc[w * 8 + 2 * e] * inv,
                                                acc[w * 8 + 2 * e + 1] * inv);
            op[w] = u.i4;
        }
    }
}

// ------------------------- launch -------------------------
extern "C" void kernel_launch(void* const* d_in, const int* in_sizes, int n_in,
                              void* d_out, int out_size) {
    const float* x           = (const float*)d_in[0];
    const float* ln1_g       = (const float*)d_in[1];
    const float* ln1_b       = (const float*)d_in[2];
    const float* qkv_w       = (const float*)d_in[3];
    const float* qkv_b       = (const float*)d_in[4];
    const float* proj_w      = (const float*)d_in[5];
    const float* proj_b      = (const float*)d_in[6];
    const float* logit_scale = (const float*)d_in[7];
    const float* ln2_g       = (const float*)d_in[8];
    const float* ln2_b       = (const float*)d_in[9];
    const float* w1          = (const float*)d_in[10];
    const float* b1          = (const float*)d_in[11];
    const float* w2          = (const float*)d_in[12];
    const float* b2          = (const float*)d_in[13];

    void *p_yb, *p_qkv, *p_attn, *p_x2, *p_y2, *p_hid, *p_wqkv, *p_wproj, *p_w1, *p_w2;
    cudaGetSymbolAddress(&p_yb, g_yb);
    cudaGetSymbolAddress(&p_qkv, g_qkv);
    cudaGetSymbolAddress(&p_attn, g_attn);
    cudaGetSymbolAddress(&p_x2, g_x2);
    cudaGetSymbolAddress(&p_y2, g_y2);
    cudaGetSymbolAddress(&p_hid, g_hid);
    cudaGetSymbolAddress(&p_wqkv, g_wqkv);
    cudaGetSymbolAddress(&p_wproj, g_wproj);
    cudaGetSymbolAddress(&p_w1, g_w1);
    cudaGetSymbolAddress(&p_w2, g_w2);

    const int ATTN_SMEM = 2 * NHEAD * SEQ * HDIM * (int)sizeof(float);  // 51200 B
    cudaFuncSetAttribute(attn_kernel, cudaFuncAttributeMaxDynamicSharedMemorySize, ATTN_SMEM);
    cudaFuncSetAttribute(mm_gemm<EPI_BF16>, cudaFuncAttributeMaxDynamicSharedMemorySize, GSMEM);
    cudaFuncSetAttribute(mm_gemm<EPI_PROJ>, cudaFuncAttributeMaxDynamicSharedMemorySize, GSMEM);
    cudaFuncSetAttribute(mm_gemm<EPI_GELU>, cudaFuncAttributeMaxDynamicSharedMemorySize, GSMEM);
    cudaFuncSetAttribute(mm_gemm<EPI_OUT>,  cudaFuncAttributeMaxDynamicSharedMemorySize, GSMEM);

    // 1) weights -> bf16, transposed to [N,K]
    convert_w_kernel<<<768, 256>>>(qkv_w, proj_w, w1, w2);
    // 2) LN1: x -> yb
    ln_kernel<<<NTOK / 8, 256>>>(x, ln1_g, ln1_b, (__nv_bfloat16*)p_yb);
    // 3) qkv GEMM: yb @ wqkv^T + b -> qkv (bf16)
    mm_gemm<EPI_BF16><<<dim3(D3 / 128, NTOK / 128), 256, GSMEM>>>(
        (const __nv_bfloat16*)p_yb, (const __nv_bfloat16*)p_wqkv, qkv_b, nullptr, p_qkv, D3, DMODEL);
    // 4) attention
    attn_kernel<<<NSEQ, 256, ATTN_SMEM>>>(logit_scale);
    // 5) proj GEMM + residual -> x2 (fp32)
    mm_gemm<EPI_PROJ><<<dim3(DMODEL / 128, NTOK / 128), 256, GSMEM>>>(
        (const __nv_bfloat16*)p_attn, (const __nv_bfloat16*)p_wproj, proj_b, x, p_x2, DMODEL, DMODEL);
    // 6) LN2: x2 -> y2
    ln_kernel<<<NTOK / 8, 256>>>((const float*)p_x2, ln2_g, ln2_b, (__nv_bfloat16*)p_y2);
    // 7) ffn1 GEMM + gelu -> hid (bf16)
    mm_gemm<EPI_GELU><<<dim3(DFFN / 128, NTOK / 128), 256, GSMEM>>>(
        (const __nv_bfloat16*)p_y2, (const __nv_bfloat16*)p_w1, b1, nullptr, p_hid, DFFN, DMODEL);
    // 8) ffn2 GEMM + residual -> out (fp32)
    mm_gemm<EPI_OUT><<<dim3(DMODEL / 128, NTOK / 128), 256, GSMEM>>>(
        (const __nv_bfloat16*)p_hid, (const __nv_bfloat16*)p_w2, b2, (const float*)p_x2, d_out, DMODEL, DFFN);
}

// round 12
// speedup vs baseline: 2.1029x; 1.0264x over previous
#include <cuda_runtime.h>
#include <cuda_bf16.h>
#include <cstdint>
#include <math.h>

// Problem dims
#define NTOK   204800          // B*T*V = 64*128*25
#define NSEQ   8192            // B*T
#define SEQ    25
#define DMODEL 256
#define NHEAD  8
#define HDIM   32
#define DFFN   1024
#define D3     768

// ------------------------- scratch (device globals) -------------------------
__device__ __nv_bfloat16 g_yb  [(size_t)NTOK * DMODEL];   // LN1 output, bf16
__device__ __nv_bfloat16 g_qkv [(size_t)NTOK * D3];       // qkv, bf16
__device__ __nv_bfloat16 g_attn[(size_t)NTOK * DMODEL];   // attention out, bf16
__device__ float         g_x2  [(size_t)NTOK * DMODEL];   // residual after proj, fp32
__device__ __nv_bfloat16 g_y2  [(size_t)NTOK * DMODEL];   // LN2 output, bf16
__device__ __nv_bfloat16 g_hid [(size_t)NTOK * DFFN];     // ffn hidden, bf16
// weights stored TRANSPOSED: [N, K] K-major (B operand, row.col mma)
__device__ __nv_bfloat16 g_wqkv [D3   * DMODEL];
__device__ __nv_bfloat16 g_wproj[DMODEL * DMODEL];
__device__ __nv_bfloat16 g_w1   [DFFN * DMODEL];
__device__ __nv_bfloat16 g_w2   [DMODEL * DFFN];

// ------------------------- ptx helpers -------------------------
__device__ __forceinline__ void cp_async16(uint32_t smem_dst, const void* gmem_src) {
    asm volatile("cp.async.cg.shared.global [%0], [%1], 16;\n" :: "r"(smem_dst), "l"(gmem_src));
}
__device__ __forceinline__ void ldmatrix_x4(uint32_t& r0, uint32_t& r1, uint32_t& r2,
                                            uint32_t& r3, uint32_t addr) {
    asm volatile("ldmatrix.sync.aligned.m8n8.x4.shared.b16 {%0,%1,%2,%3}, [%4];"
                 : "=r"(r0), "=r"(r1), "=r"(r2), "=r"(r3) : "r"(addr));
}
__device__ __forceinline__ void mma16816(float& d0, float& d1, float& d2, float& d3,
                                         uint32_t a0, uint32_t a1, uint32_t a2, uint32_t a3,
                                         uint32_t b0, uint32_t b1) {
    asm volatile(
        "mma.sync.aligned.m16n8k16.row.col.f32.bf16.bf16.f32 "
        "{%0,%1,%2,%3}, {%4,%5,%6,%7}, {%8,%9}, {%0,%1,%2,%3};"
        : "+f"(d0), "+f"(d1), "+f"(d2), "+f"(d3)
        : "r"(a0), "r"(a1), "r"(a2), "r"(a3), "r"(b0), "r"(b1));
}

// ------------------------- weight fp32 -> bf16 (TRANSPOSED to [N,K]) -----------
__global__ void convert_w_kernel(const float* __restrict__ qkv_w,
                                 const float* __restrict__ proj_w,
                                 const float* __restrict__ w1,
                                 const float* __restrict__ w2) {
    int i0 = blockIdx.x * blockDim.x + threadIdx.x;
    int stride = gridDim.x * blockDim.x;
    for (int i = i0; i < D3 * DMODEL; i += stride) {
        int n = i >> 8, k = i & 255;
        g_wqkv[i] = __float2bfloat16(qkv_w[k * D3 + n]);
    }
    for (int i = i0; i < DMODEL * DMODEL; i += stride) {
        int n = i >> 8, k = i & 255;
        g_wproj[i] = __float2bfloat16(proj_w[k * DMODEL + n]);
    }
    for (int i = i0; i < DFFN * DMODEL; i += stride) {
        int n = i >> 8, k = i & 255;
        g_w1[i] = __float2bfloat16(w1[k * DFFN + n]);
    }
    for (int i = i0; i < DMODEL * DFFN; i += stride) {
        int n = i >> 10, k = i & 1023;
        g_w2[i] = __float2bfloat16(w2[k * DMODEL + n]);
    }
}

// ------------------------- LayerNorm (warp per row, D=256) -------------------------
__global__ __launch_bounds__(256) void ln_kernel(const float* __restrict__ X,
                                                 const float* __restrict__ gam,
                                                 const float* __restrict__ bet,
                                                 __nv_bfloat16* __restrict__ Y) {
    int warp = (blockIdx.x * blockDim.x + threadIdx.x) >> 5;
    int lane = threadIdx.x & 31;
    if (warp >= NTOK) return;
    const float4* xp = (const float4*)(X + (size_t)warp * DMODEL);
    float4 v0 = xp[lane * 2];
    float4 v1 = xp[lane * 2 + 1];
    float s = v0.x + v0.y + v0.z + v0.w + v1.x + v1.y + v1.z + v1.w;
    #pragma unroll
    for (int o = 16; o > 0; o >>= 1) s += __shfl_xor_sync(0xffffffffu, s, o);
    float m = s * (1.0f / 256.0f);
    float d0x = v0.x - m, d0y = v0.y - m, d0z = v0.z - m, d0w = v0.w - m;
    float d1x = v1.x - m, d1y = v1.y - m, d1z = v1.z - m, d1w = v1.w - m;
    float vs = d0x*d0x + d0y*d0y + d0z*d0z + d0w*d0w + d1x*d1x + d1y*d1y + d1z*d1z + d1w*d1w;
    #pragma unroll
    for (int o = 16; o > 0; o >>= 1) vs += __shfl_xor_sync(0xffffffffu, vs, o);
    float rstd = rsqrtf(vs * (1.0f / 256.0f) + 1e-5f);
    const float4* gp = (const float4*)gam;
    const float4* bp = (const float4*)bet;
    float4 g0 = gp[lane * 2], g1 = gp[lane * 2 + 1];
    float4 b0 = bp[lane * 2], b1 = bp[lane * 2 + 1];
    float y[8];
    y[0] = d0x * rstd * g0.x + b0.x;  y[1] = d0y * rstd * g0.y + b0.y;
    y[2] = d0z * rstd * g0.z + b0.z;  y[3] = d0w * rstd * g0.w + b0.w;
    y[4] = d1x * rstd * g1.x + b1.x;  y[5] = d1y * rstd * g1.y + b1.y;
    y[6] = d1z * rstd * g1.z + b1.z;  y[7] = d1w * rstd * g1.w + b1.w;
    union { int4 i4; __nv_bfloat162 h2[4]; } u;
    u.h2[0] = __floats2bfloat162_rn(y[0], y[1]);
    u.h2[1] = __floats2bfloat162_rn(y[2], y[3]);
    u.h2[2] = __floats2bfloat162_rn(y[4], y[5]);
    u.h2[3] = __floats2bfloat162_rn(y[6], y[7]);
    *((int4*)(Y + (size_t)warp * DMODEL + lane * 8)) = u.i4;
}

// ------------------------- mma.sync GEMM -------------------------
// C[M,N] = A[M,K] @ Bw[N,K]^T + bias (+ epilogue).
// 128x128 CTA tile, BK=32, 3-stage cp.async pipeline, 8 warps, warp tile 32x64.
// A and B fragments both via ldmatrix (conflict-free at ROWB=80 pitch).
enum { EPI_BF16 = 0, EPI_PROJ = 1, EPI_GELU = 2, EPI_OUT = 3 };

#define ROWB   80                    // padded row pitch in bytes (32 bf16 + 8 pad)
#define STAGE_A 10240                // 128 * 80
#define STAGE  20480                 // A + B per stage
#define GSMEM  61440                 // 3 stages

template <int EPI>
__global__ __launch_bounds__(256) void mm_gemm(
    const __nv_bfloat16* __restrict__ A,
    const __nv_bfloat16* __restrict__ Bw,
    const float* __restrict__ bias,
    const float* __restrict__ res,
    void* __restrict__ out, int N, int K)
{
    extern __shared__ __align__(128) char smem[];
    const uint32_t sb = (uint32_t)__cvta_generic_to_shared(smem);
    const int t = threadIdx.x, wid = t >> 5, lane = t & 31;
    const int wm = wid & 3;          // 0..3 -> 32-row slab
    const int wn = wid >> 2;         // 0..1 -> 64-col slab
    const size_t m0 = (size_t)blockIdx.y * 128;
    const int n0 = blockIdx.x * 128;
    const int C = K >> 5;            // BK=32 chunks

    auto load_chunk = [&](int c, int s) {
        const uint32_t base = sb + (uint32_t)s * STAGE;
        const int k0 = c << 5;
        #pragma unroll
        for (int i = 0; i < 2; i++) {
            int idx = i * 256 + t;
            int r = idx >> 2, cc = idx & 3;
            cp_async16(base + (uint32_t)(r * ROWB + cc * 16),
                       A + (m0 + r) * K + k0 + cc * 8);
        }
        #pragma unroll
        for (int i = 0; i < 2; i++) {
            int idx = i * 256 + t;
            int r = idx >> 2, cc = idx & 3;
            cp_async16(base + STAGE_A + (uint32_t)(r * ROWB + cc * 16),
                       Bw + (size_t)(n0 + r) * K + k0 + cc * 8);
        }
        asm volatile("cp.async.commit_group;");
    };

    float acc[2][8][4];
    #pragma unroll
    for (int i = 0; i < 2; i++)
        #pragma unroll
        for (int j = 0; j < 8; j++)
            #pragma unroll
            for (int e = 0; e < 4; e++) acc[i][j][e] = 0.0f;

    load_chunk(0, 0);
    load_chunk(1, 1);

    // ldmatrix lane roles for B: g = lane>>3, row_in = lane&7
    const int b_g = lane >> 3;
    const int b_row = lane & 7;
    const int b_noff = (b_g >> 1) * 8 + b_row;   // n offset within 16-col group
    const int b_kc16 = (b_g & 1) * 16;           // 16B k-chunk select

    for (int c = 0; c < C; c++) {
        if (c < C - 1) { asm volatile("cp.async.wait_group 1;"); }
        else           { asm volatile("cp.async.wait_group 0;"); }
        __syncthreads();
        if (c + 2 < C) load_chunk(c + 2, (c + 2) % 3);

        const uint32_t aBase = sb + (uint32_t)(c % 3) * STAGE;
        const uint32_t bBase = aBase + STAGE_A;

        #pragma unroll
        for (int ks = 0; ks < 2; ks++) {
            uint32_t a[2][4];
            #pragma unroll
            for (int i = 0; i < 2; i++) {
                uint32_t addr = aBase
                    + (uint32_t)((wm * 32 + i * 16 + (lane & 15)) * ROWB
                                 + ks * 32 + (lane >> 4) * 16);
                ldmatrix_x4(a[i][0], a[i][1], a[i][2], a[i][3], addr);
            }
            // B: two 32-col halves, 2 ldmatrix.x4 each (4 n8-groups/half)
            #pragma unroll
            for (int half = 0; half < 2; half++) {
                uint32_t bb[4][2];
                #pragma unroll
                for (int g4 = 0; g4 < 2; g4++) {
                    int nrow = wn * 64 + half * 32 + g4 * 16 + b_noff;
                    uint32_t addr = bBase + (uint32_t)(nrow * ROWB + ks * 32 + b_kc16);
                    ldmatrix_x4(bb[g4 * 2][0], bb[g4 * 2][1],
                                bb[g4 * 2 + 1][0], bb[g4 * 2 + 1][1], addr);
                }
                #pragma unroll
                for (int j = 0; j < 4; j++) {
                    int jj = half * 4 + j;
                    #pragma unroll
                    for (int i = 0; i < 2; i++)
                        mma16816(acc[i][jj][0], acc[i][jj][1], acc[i][jj][2], acc[i][jj][3],
                                 a[i][0], a[i][1], a[i][2], a[i][3], bb[j][0], bb[j][1]);
                }
            }
        }
        __syncthreads();
    }

    // epilogue straight from fragments
    const int qrow = lane >> 2;
    const int qcol = (lane & 3) * 2;
    #pragma unroll
    for (int i = 0; i < 2; i++) {
        #pragma unroll
        for (int j = 0; j < 8; j++) {
            int col = n0 + wn * 64 + j * 8 + qcol;
            float2 bb = *(const float2*)(bias + col);
            #pragma unroll
            for (int h = 0; h < 2; h++) {
                size_t row = m0 + wm * 32 + i * 16 + qrow + h * 8;
                float v0 = acc[i][j][2 * h + 0] + bb.x;
                float v1 = acc[i][j][2 * h + 1] + bb.y;
                size_t o = row * (size_t)N + col;
                if (EPI == EPI_BF16) {
                    *(__nv_bfloat162*)((__nv_bfloat16*)out + o) = __floats2bfloat162_rn(v0, v1);
                } else if (EPI == EPI_GELU) {
                    v0 = 0.5f * v0 * (1.0f + erff(v0 * 0.70710678118654752f));
                    v1 = 0.5f * v1 * (1.0f + erff(v1 * 0.70710678118654752f));
                    *(__nv_bfloat162*)((__nv_bfloat16*)out + o) = __floats2bfloat162_rn(v0, v1);
                } else {
                    float2 rr = *(const float2*)(res + o);
                    float2 ov = make_float2(v0 + rr.x, v1 + rr.y);
                    *(float2*)((float*)out + o) = ov;
                }
            }
        }
    }
}

// ------------------------- Cosine attention -------------------------
// Block per sequence, warp per head. qkv tile staged through smem with
// coalesced loads; per-lane reads are conflict-free LDS.32 (pitch 385 words).
// k/v float arrays padded to pitch 36 -> conflict-free STS.128 / LDS broadcast.
#define STG_PITCH 385                 // uint32 words per staged row (384 + 1 pad)
#define KV_PITCH  36                  // floats per k/v row (32 + 4 pad)
#define KV_HEAD   (SEQ * KV_PITCH)    // 900 floats per head
#define ATTN_SMEM_WORDS (9632 + 2 * NHEAD * KV_HEAD)   // 9632 + 14400 = 24032
#define ATTN_SMEM_BYTES (ATTN_SMEM_WORDS * 4)          // 96128 B

__global__ __launch_bounds__(256) void attn_kernel(const float* __restrict__ logit_scale) {
    extern __shared__ float sm[];
    uint32_t* stage = (uint32_t*)sm;             // [25][385] words (bf16x2)
    float* kf = sm + 9632;                        // [8][25][36]
    float* vf = kf + NHEAD * KV_HEAD;             // [8][25][36]

    const int n = blockIdx.x;
    const int t = threadIdx.x;
    const int h = t >> 5;
    const int lane = t & 31;

    // ---- coalesced stage of the 25x768 bf16 qkv tile (2400 int4) ----
    {
        const int4* gq = (const int4*)(g_qkv + (size_t)n * SEQ * D3);
        #pragma unroll
        for (int i = 0; i < 10; i++) {
            int idx = i * 256 + t;
            if (idx < 2400) {
                int r = idx / 96, c = idx % 96;        // c in int4 units
                int4 v4 = gq[r * 96 + c];
                uint32_t* d = stage + r * STG_PITCH + c * 4;
                d[0] = ((const uint32_t*)&v4)[0];
                d[1] = ((const uint32_t*)&v4)[1];
                d[2] = ((const uint32_t*)&v4)[2];
                d[3] = ((const uint32_t*)&v4)[3];
            }
        }
    }
    __syncthreads();

    float scale = expf(fminf(logit_scale[h], 4.6051701859880914f));  // log(100)
    float* khh = kf + h * KV_HEAD;
    float* vhh = vf + h * KV_HEAD;

    float q[32];
    if (lane < SEQ) {
        // conflict-free LDS.32: bank = (lane*385 + off) % 32 = (lane + off) % 32
        const uint32_t* row = stage + lane * STG_PITCH + h * 16;
        float kv[32], vv[32];
        float qs = 0.0f, ks = 0.0f;
        #pragma unroll
        for (int c = 0; c < 16; c++) {
            float2 fq = __bfloat1622float2(*(const __nv_bfloat162*)&row[c]);
            float2 fk = __bfloat1622float2(*(const __nv_bfloat162*)&row[c + 128]);
            float2 fv = __bfloat1622float2(*(const __nv_bfloat162*)&row[c + 256]);
            int d = c * 2;
            q[d] = fq.x;   q[d + 1] = fq.y;
            kv[d] = fk.x;  kv[d + 1] = fk.y;
            vv[d] = fv.x;  vv[d + 1] = fv.y;
            qs += fq.x * fq.x + fq.y * fq.y;
            ks += fk.x * fk.x + fk.y * fk.y;
        }
        float qf = scale * 0.17677669529663687f / fmaxf(sqrtf(qs), 1e-12f);  // * 1/sqrt(32)
        float kf_ = 1.0f / fmaxf(sqrtf(ks), 1e-12f);
        float4* kp4 = (float4*)(khh + lane * KV_PITCH);
        float4* vp4 = (float4*)(vhh + lane * KV_PITCH);
        #pragma unroll
        for (int w = 0; w < 8; w++) {
            int d = w * 4;
            q[d] *= qf; q[d+1] *= qf; q[d+2] *= qf; q[d+3] *= qf;
            kp4[w] = make_float4(kv[d] * kf_, kv[d+1] * kf_, kv[d+2] * kf_, kv[d+3] * kf_);
            vp4[w] = make_float4(vv[d], vv[d+1], vv[d+2], vv[d+3]);
        }
    }
    __syncwarp();

    if (lane < SEQ) {
        float lg[SEQ];
        float mx = -1e30f;
        #pragma unroll
        for (int j = 0; j < SEQ; j++) {
            const float4* kp4 = (const float4*)(khh + j * KV_PITCH);
            float dot = 0.0f;
            #pragma unroll
            for (int tt = 0; tt < 8; tt++) {
                float4 kvv = kp4[tt];
                dot += q[tt * 4 + 0] * kvv.x + q[tt * 4 + 1] * kvv.y
                     + q[tt * 4 + 2] * kvv.z + q[tt * 4 + 3] * kvv.w;
            }
            lg[j] = dot;
            mx = fmaxf(mx, dot);
        }
        float ssum = 0.0f;
        #pragma unroll
        for (int j = 0; j < SEQ; j++) {
            lg[j] = expf(lg[j] - mx);
            ssum += lg[j];
        }
        float inv = 1.0f / ssum;

        float acc[32];
        #pragma unroll
        for (int d = 0; d < 32; d++) acc[d] = 0.0f;
        #pragma unroll
        for (int j = 0; j < SEQ; j++) {
            float a = lg[j];
            const float4* vp4 = (const float4*)(vhh + j * KV_PITCH);
            #pragma unroll
            for (int tt = 0; tt < 8; tt++) {
                float4 vvv = vp4[tt];
                acc[tt * 4 + 0] += a * vvv.x;
                acc[tt * 4 + 1] += a * vvv.y;
                acc[tt * 4 + 2] += a * vvv.z;
                acc[tt * 4 + 3] += a * vvv.w;
            }
        }
        union { int4 i4; __nv_bfloat162 h2[4]; } u;
        int4* op = (int4*)(g_attn + ((size_t)n * SEQ + lane) * DMODEL + h * HDIM);
        #pragma unroll
        for (int w = 0; w < 4; w++) {
            #pragma unroll
            for (int e = 0; e < 4; e++)
                u.h2[e] = __floats2bfloat162_rn(acc[w * 8 + 2 * e] * inv,
                                                acc[w * 8 + 2 * e + 1] * inv);
            op[w] = u.i4;
        }
    }
}

// ------------------------- launch -------------------------
extern "C" void kernel_launch(void* const* d_in, const int* in_sizes, int n_in,
                              void* d_out, int out_size) {
    const float* x           = (const float*)d_in[0];
    const float* ln1_g       = (const float*)d_in[1];
    const float* ln1_b       = (const float*)d_in[2];
    const float* qkv_w       = (const float*)d_in[3];
    const float* qkv_b       = (const float*)d_in[4];
    const float* proj_w      = (const float*)d_in[5];
    const float* proj_b      = (const float*)d_in[6];
    const float* logit_scale = (const float*)d_in[7];
    const float* ln2_g       = (const float*)d_in[8];
    const float* ln2_b       = (const float*)d_in[9];
    const float* w1          = (const float*)d_in[10];
    const float* b1          = (const float*)d_in[11];
    const float* w2          = (const float*)d_in[12];
    const float* b2          = (const float*)d_in[13];

    void *p_yb, *p_qkv, *p_attn, *p_x2, *p_y2, *p_hid, *p_wqkv, *p_wproj, *p_w1, *p_w2;
    cudaGetSymbolAddress(&p_yb, g_yb);
    cudaGetSymbolAddress(&p_qkv, g_qkv);
    cudaGetSymbolAddress(&p_attn, g_attn);
    cudaGetSymbolAddress(&p_x2, g_x2);
    cudaGetSymbolAddress(&p_y2, g_y2);
    cudaGetSymbolAddress(&p_hid, g_hid);
    cudaGetSymbolAddress(&p_wqkv, g_wqkv);
    cudaGetSymbolAddress(&p_wproj, g_wproj);
    cudaGetSymbolAddress(&p_w1, g_w1);
    cudaGetSymbolAddress(&p_w2, g_w2);

    cudaFuncSetAttribute(attn_kernel, cudaFuncAttributeMaxDynamicSharedMemorySize, ATTN_SMEM_BYTES);
    cudaFuncSetAttribute(mm_gemm<EPI_BF16>, cudaFuncAttributeMaxDynamicSharedMemorySize, GSMEM);
    cudaFuncSetAttribute(mm_gemm<EPI_PROJ>, cudaFuncAttributeMaxDynamicSharedMemorySize, GSMEM);
    cudaFuncSetAttribute(mm_gemm<EPI_GELU>, cudaFuncAttributeMaxDynamicSharedMemorySize, GSMEM);
    cudaFuncSetAttribute(mm_gemm<EPI_OUT>,  cudaFuncAttributeMaxDynamicSharedMemorySize, GSMEM);

    // 1) weights -> bf16, transposed to [N,K]
    convert_w_kernel<<<768, 256>>>(qkv_w, proj_w, w1, w2);
    // 2) LN1: x -> yb
    ln_kernel<<<NTOK / 8, 256>>>(x, ln1_g, ln1_b, (__nv_bfloat16*)p_yb);
    // 3) qkv GEMM: yb @ wqkv^T + b -> qkv (bf16)
    mm_gemm<EPI_BF16><<<dim3(D3 / 128, NTOK / 128), 256, GSMEM>>>(
        (const __nv_bfloat16*)p_yb, (const __nv_bfloat16*)p_wqkv, qkv_b, nullptr, p_qkv, D3, DMODEL);
    // 4) attention
    attn_kernel<<<NSEQ, 256, ATTN_SMEM_BYTES>>>(logit_scale);
    // 5) proj GEMM + residual -> x2 (fp32)
    mm_gemm<EPI_PROJ><<<dim3(DMODEL / 128, NTOK / 128), 256, GSMEM>>>(
        (const __nv_bfloat16*)p_attn, (const __nv_bfloat16*)p_wproj, proj_b, x, p_x2, DMODEL, DMODEL);
    // 6) LN2: x2 -> y2
    ln_kernel<<<NTOK / 8, 256>>>((const float*)p_x2, ln2_g, ln2_b, (__nv_bfloat16*)p_y2);
    // 7) ffn1 GEMM + gelu -> hid (bf16)
    mm_gemm<EPI_GELU><<<dim3(DFFN / 128, NTOK / 128), 256, GSMEM>>>(
        (const __nv_bfloat16*)p_y2, (const __nv_bfloat16*)p_w1, b1, nullptr, p_hid, DFFN, DMODEL);
    // 8) ffn2 GEMM + residual -> out (fp32)
    mm_gemm<EPI_OUT><<<dim3(DMODEL / 128, NTOK / 128), 256, GSMEM>>>(
        (const __nv_bfloat16*)p_hid, (const __nv_bfloat16*)p_w2, b2, (const float*)p_x2, d_out, DMODEL, DFFN);
}

// round 13
// speedup vs baseline: 2.1618x; 1.0280x over previous
#include <cuda_runtime.h>
#include <cuda_bf16.h>
#include <cstdint>
#include <math.h>

// Problem dims
#define NTOK   204800          // B*T*V = 64*128*25
#define NSEQ   8192            // B*T
#define SEQ    25
#define DMODEL 256
#define NHEAD  8
#define HDIM   32
#define DFFN   1024
#define D3     768

// ------------------------- scratch (device globals) -------------------------
__device__ __nv_bfloat16 g_yb  [(size_t)NTOK * DMODEL];   // LN1 output, bf16
__device__ __nv_bfloat16 g_qkv [(size_t)NTOK * D3];       // qkv, bf16
__device__ __nv_bfloat16 g_attn[(size_t)NTOK * DMODEL];   // attention out, bf16
__device__ float         g_x2  [(size_t)NTOK * DMODEL];   // residual after proj, fp32
__device__ __nv_bfloat16 g_y2  [(size_t)NTOK * DMODEL];   // LN2 output, bf16
__device__ __nv_bfloat16 g_hid [(size_t)NTOK * DFFN];     // ffn hidden, bf16
// weights stored TRANSPOSED: [N, K] K-major (B operand, row.col mma)
__device__ __nv_bfloat16 g_wqkv [D3   * DMODEL];
__device__ __nv_bfloat16 g_wproj[DMODEL * DMODEL];
__device__ __nv_bfloat16 g_w1   [DFFN * DMODEL];
__device__ __nv_bfloat16 g_w2   [DMODEL * DFFN];

// ------------------------- ptx helpers -------------------------
__device__ __forceinline__ void cp_async16(uint32_t smem_dst, const void* gmem_src) {
    asm volatile("cp.async.cg.shared.global [%0], [%1], 16;\n" :: "r"(smem_dst), "l"(gmem_src));
}
__device__ __forceinline__ void ldmatrix_x4(uint32_t& r0, uint32_t& r1, uint32_t& r2,
                                            uint32_t& r3, uint32_t addr) {
    asm volatile("ldmatrix.sync.aligned.m8n8.x4.shared.b16 {%0,%1,%2,%3}, [%4];"
                 : "=r"(r0), "=r"(r1), "=r"(r2), "=r"(r3) : "r"(addr));
}
__device__ __forceinline__ void mma16816(float& d0, float& d1, float& d2, float& d3,
                                         uint32_t a0, uint32_t a1, uint32_t a2, uint32_t a3,
                                         uint32_t b0, uint32_t b1) {
    asm volatile(
        "mma.sync.aligned.m16n8k16.row.col.f32.bf16.bf16.f32 "
        "{%0,%1,%2,%3}, {%4,%5,%6,%7}, {%8,%9}, {%0,%1,%2,%3};"
        : "+f"(d0), "+f"(d1), "+f"(d2), "+f"(d3)
        : "r"(a0), "r"(a1), "r"(a2), "r"(a3), "r"(b0), "r"(b1));
}

// ------------------------- weight fp32 -> bf16 (TRANSPOSED to [N,K]) -----------
__global__ void convert_w_kernel(const float* __restrict__ qkv_w,
                                 const float* __restrict__ proj_w,
                                 const float* __restrict__ w1,
                                 const float* __restrict__ w2) {
    int i0 = blockIdx.x * blockDim.x + threadIdx.x;
    int stride = gridDim.x * blockDim.x;
    for (int i = i0; i < D3 * DMODEL; i += stride) {
        int n = i >> 8, k = i & 255;
        g_wqkv[i] = __float2bfloat16(qkv_w[k * D3 + n]);
    }
    for (int i = i0; i < DMODEL * DMODEL; i += stride) {
        int n = i >> 8, k = i & 255;
        g_wproj[i] = __float2bfloat16(proj_w[k * DMODEL + n]);
    }
    for (int i = i0; i < DFFN * DMODEL; i += stride) {
        int n = i >> 8, k = i & 255;
        g_w1[i] = __float2bfloat16(w1[k * DFFN + n]);
    }
    for (int i = i0; i < DMODEL * DFFN; i += stride) {
        int n = i >> 10, k = i & 1023;
        g_w2[i] = __float2bfloat16(w2[k * DMODEL + n]);
    }
}

// ------------------------- LayerNorm (warp per row, D=256) -------------------------
__global__ __launch_bounds__(256) void ln_kernel(const float* __restrict__ X,
                                                 const float* __restrict__ gam,
                                                 const float* __restrict__ bet,
                                                 __nv_bfloat16* __restrict__ Y) {
    int warp = (blockIdx.x * blockDim.x + threadIdx.x) >> 5;
    int lane = threadIdx.x & 31;
    if (warp >= NTOK) return;
    const float4* xp = (const float4*)(X + (size_t)warp * DMODEL);
    float4 v0 = xp[lane * 2];
    float4 v1 = xp[lane * 2 + 1];
    float s = v0.x + v0.y + v0.z + v0.w + v1.x + v1.y + v1.z + v1.w;
    #pragma unroll
    for (int o = 16; o > 0; o >>= 1) s += __shfl_xor_sync(0xffffffffu, s, o);
    float m = s * (1.0f / 256.0f);
    float d0x = v0.x - m, d0y = v0.y - m, d0z = v0.z - m, d0w = v0.w - m;
    float d1x = v1.x - m, d1y = v1.y - m, d1z = v1.z - m, d1w = v1.w - m;
    float vs = d0x*d0x + d0y*d0y + d0z*d0z + d0w*d0w + d1x*d1x + d1y*d1y + d1z*d1z + d1w*d1w;
    #pragma unroll
    for (int o = 16; o > 0; o >>= 1) vs += __shfl_xor_sync(0xffffffffu, vs, o);
    float rstd = rsqrtf(vs * (1.0f / 256.0f) + 1e-5f);
    const float4* gp = (const float4*)gam;
    const float4* bp = (const float4*)bet;
    float4 g0 = gp[lane * 2], g1 = gp[lane * 2 + 1];
    float4 b0 = bp[lane * 2], b1 = bp[lane * 2 + 1];
    float y[8];
    y[0] = d0x * rstd * g0.x + b0.x;  y[1] = d0y * rstd * g0.y + b0.y;
    y[2] = d0z * rstd * g0.z + b0.z;  y[3] = d0w * rstd * g0.w + b0.w;
    y[4] = d1x * rstd * g1.x + b1.x;  y[5] = d1y * rstd * g1.y + b1.y;
    y[6] = d1z * rstd * g1.z + b1.z;  y[7] = d1w * rstd * g1.w + b1.w;
    union { int4 i4; __nv_bfloat162 h2[4]; } u;
    u.h2[0] = __floats2bfloat162_rn(y[0], y[1]);
    u.h2[1] = __floats2bfloat162_rn(y[2], y[3]);
    u.h2[2] = __floats2bfloat162_rn(y[4], y[5]);
    u.h2[3] = __floats2bfloat162_rn(y[6], y[7]);
    *((int4*)(Y + (size_t)warp * DMODEL + lane * 8)) = u.i4;
}

// ------------------------- mma.sync GEMM -------------------------
// C[M,N] = A[M,K] @ Bw[N,K]^T + bias (+ epilogue).
// 128x128 CTA tile, BK=32, FOUR-stage cp.async pipeline with ONE
// __syncthreads per chunk (wait_group 2 keeps compute 2 chunks behind the
// prefetch head). 8 warps, warp tile 32x64, ldmatrix A+B.
enum { EPI_BF16 = 0, EPI_PROJ = 1, EPI_GELU = 2, EPI_OUT = 3 };

#define ROWB   80                    // padded row pitch in bytes (32 bf16 + 8 pad)
#define STAGE_A 10240                // 128 * 80
#define STAGE  20480                 // A + B per stage
#define NSTAGE 4
#define GSMEM  (NSTAGE * STAGE)      // 81920

template <int EPI>
__global__ __launch_bounds__(256) void mm_gemm(
    const __nv_bfloat16* __restrict__ A,
    const __nv_bfloat16* __restrict__ Bw,
    const float* __restrict__ bias,
    const float* __restrict__ res,
    void* __restrict__ out, int N, int K)
{
    extern __shared__ __align__(128) char smem[];
    const uint32_t sb = (uint32_t)__cvta_generic_to_shared(smem);
    const int t = threadIdx.x, wid = t >> 5, lane = t & 31;
    const int wm = wid & 3;          // 0..3 -> 32-row slab
    const int wn = wid >> 2;         // 0..1 -> 64-col slab
    const size_t m0 = (size_t)blockIdx.y * 128;
    const int n0 = blockIdx.x * 128;
    const int C = K >> 5;            // BK=32 chunks

    auto load_chunk = [&](int c, int s) {
        const uint32_t base = sb + (uint32_t)s * STAGE;
        const int k0 = c << 5;
        #pragma unroll
        for (int i = 0; i < 2; i++) {
            int idx = i * 256 + t;
            int r = idx >> 2, cc = idx & 3;
            cp_async16(base + (uint32_t)(r * ROWB + cc * 16),
                       A + (m0 + r) * K + k0 + cc * 8);
        }
        #pragma unroll
        for (int i = 0; i < 2; i++) {
            int idx = i * 256 + t;
            int r = idx >> 2, cc = idx & 3;
            cp_async16(base + STAGE_A + (uint32_t)(r * ROWB + cc * 16),
                       Bw + (size_t)(n0 + r) * K + k0 + cc * 8);
        }
        asm volatile("cp.async.commit_group;");
    };

    float acc[2][8][4];
    #pragma unroll
    for (int i = 0; i < 2; i++)
        #pragma unroll
        for (int j = 0; j < 8; j++)
            #pragma unroll
            for (int e = 0; e < 4; e++) acc[i][j][e] = 0.0f;

    // prefetch first 3 stages
    load_chunk(0, 0);
    if (C > 1) load_chunk(1, 1);
    if (C > 2) load_chunk(2, 2);

    // ldmatrix lane roles for B
    const int b_g = lane >> 3;
    const int b_row = lane & 7;
    const int b_noff = (b_g >> 1) * 8 + b_row;
    const int b_kc16 = (b_g & 1) * 16;

    for (int c = 0; c < C; c++) {
        // groups issued so far: min(c+3, C). need group c complete.
        if (c < C - 2)      { asm volatile("cp.async.wait_group 2;"); }
        else if (c == C - 2){ asm volatile("cp.async.wait_group 1;"); }
        else                { asm volatile("cp.async.wait_group 0;"); }
        __syncthreads();
        // safe to overwrite stage (c+3)%4 == (c-1)%4: every warp passed the
        // barrier above only after finishing compute on chunk c-1.
        if (c + 3 < C) load_chunk(c + 3, (c + 3) & 3);

        const uint32_t aBase = sb + (uint32_t)(c & 3) * STAGE;
        const uint32_t bBase = aBase + STAGE_A;

        #pragma unroll
        for (int ks = 0; ks < 2; ks++) {
            uint32_t a[2][4];
            #pragma unroll
            for (int i = 0; i < 2; i++) {
                uint32_t addr = aBase
                    + (uint32_t)((wm * 32 + i * 16 + (lane & 15)) * ROWB
                                 + ks * 32 + (lane >> 4) * 16);
                ldmatrix_x4(a[i][0], a[i][1], a[i][2], a[i][3], addr);
            }
            #pragma unroll
            for (int half = 0; half < 2; half++) {
                uint32_t bb[4][2];
                #pragma unroll
                for (int g4 = 0; g4 < 2; g4++) {
                    int nrow = wn * 64 + half * 32 + g4 * 16 + b_noff;
                    uint32_t addr = bBase + (uint32_t)(nrow * ROWB + ks * 32 + b_kc16);
                    ldmatrix_x4(bb[g4 * 2][0], bb[g4 * 2][1],
                                bb[g4 * 2 + 1][0], bb[g4 * 2 + 1][1], addr);
                }
                #pragma unroll
                for (int j = 0; j < 4; j++) {
                    int jj = half * 4 + j;
                    #pragma unroll
                    for (int i = 0; i < 2; i++)
                        mma16816(acc[i][jj][0], acc[i][jj][1], acc[i][jj][2], acc[i][jj][3],
                                 a[i][0], a[i][1], a[i][2], a[i][3], bb[j][0], bb[j][1]);
                }
            }
        }
    }

    // epilogue straight from fragments
    const int qrow = lane >> 2;
    const int qcol = (lane & 3) * 2;
    #pragma unroll
    for (int i = 0; i < 2; i++) {
        #pragma unroll
        for (int j = 0; j < 8; j++) {
            int col = n0 + wn * 64 + j * 8 + qcol;
            float2 bb = *(const float2*)(bias + col);
            #pragma unroll
            for (int h = 0; h < 2; h++) {
                size_t row = m0 + wm * 32 + i * 16 + qrow + h * 8;
                float v0 = acc[i][j][2 * h + 0] + bb.x;
                float v1 = acc[i][j][2 * h + 1] + bb.y;
                size_t o = row * (size_t)N + col;
                if (EPI == EPI_BF16) {
                    *(__nv_bfloat162*)((__nv_bfloat16*)out + o) = __floats2bfloat162_rn(v0, v1);
                } else if (EPI == EPI_GELU) {
                    v0 = 0.5f * v0 * (1.0f + erff(v0 * 0.70710678118654752f));
                    v1 = 0.5f * v1 * (1.0f + erff(v1 * 0.70710678118654752f));
                    *(__nv_bfloat162*)((__nv_bfloat16*)out + o) = __floats2bfloat162_rn(v0, v1);
                } else {
                    float2 rr = *(const float2*)(res + o);
                    float2 ov = make_float2(v0 + rr.x, v1 + rr.y);
                    *(float2*)((float*)out + o) = ov;
                }
            }
        }
    }
}

// ------------------------- Cosine attention -------------------------
// Block per sequence, warp per head. qkv tile staged through smem with
// coalesced loads; per-lane reads are conflict-free LDS.32 (pitch 385 words).
// k/v float arrays padded to pitch 36 -> conflict-free STS.128 / LDS broadcast.
#define STG_PITCH 385                 // uint32 words per staged row (384 + 1 pad)
#define KV_PITCH  36                  // floats per k/v row (32 + 4 pad)
#define KV_HEAD   (SEQ * KV_PITCH)    // 900 floats per head
#define ATTN_SMEM_WORDS (9632 + 2 * NHEAD * KV_HEAD)   // 9632 + 14400 = 24032
#define ATTN_SMEM_BYTES (ATTN_SMEM_WORDS * 4)          // 96128 B

__global__ __launch_bounds__(256) void attn_kernel(const float* __restrict__ logit_scale) {
    extern __shared__ float sm[];
    uint32_t* stage = (uint32_t*)sm;             // [25][385] words (bf16x2)
    float* kf = sm + 9632;                        // [8][25][36]
    float* vf = kf + NHEAD * KV_HEAD;             // [8][25][36]

    const int n = blockIdx.x;
    const int t = threadIdx.x;
    const int h = t >> 5;
    const int lane = t & 31;

    // ---- coalesced stage of the 25x768 bf16 qkv tile (2400 int4) ----
    {
        const int4* gq = (const int4*)(g_qkv + (size_t)n * SEQ * D3);
        #pragma unroll
        for (int i = 0; i < 10; i++) {
            int idx = i * 256 + t;
            if (idx < 2400) {
                int r = idx / 96, c = idx % 96;        // c in int4 units
                int4 v4 = gq[r * 96 + c];
                uint32_t* d = stage + r * STG_PITCH + c * 4;
                d[0] = ((const uint32_t*)&v4)[0];
                d[1] = ((const uint32_t*)&v4)[1];
                d[2] = ((const uint32_t*)&v4)[2];
                d[3] = ((const uint32_t*)&v4)[3];
            }
        }
    }
    __syncthreads();

    float scale = expf(fminf(logit_scale[h], 4.6051701859880914f));  // log(100)
    float* khh = kf + h * KV_HEAD;
    float* vhh = vf + h * KV_HEAD;

    float q[32];
    if (lane < SEQ) {
        const uint32_t* row = stage + lane * STG_PITCH + h * 16;
        float kv[32], vv[32];
        float qs = 0.0f, ks = 0.0f;
        #pragma unroll
        for (int c = 0; c < 16; c++) {
            float2 fq = __bfloat1622float2(*(const __nv_bfloat162*)&row[c]);
            float2 fk = __bfloat1622float2(*(const __nv_bfloat162*)&row[c + 128]);
            float2 fv = __bfloat1622float2(*(const __nv_bfloat162*)&row[c + 256]);
            int d = c * 2;
            q[d] = fq.x;   q[d + 1] = fq.y;
            kv[d] = fk.x;  kv[d + 1] = fk.y;
            vv[d] = fv.x;  vv[d + 1] = fv.y;
            qs += fq.x * fq.x + fq.y * fq.y;
            ks += fk.x * fk.x + fk.y * fk.y;
        }
        float qf = scale * 0.17677669529663687f / fmaxf(sqrtf(qs), 1e-12f);  // * 1/sqrt(32)
        float kf_ = 1.0f / fmaxf(sqrtf(ks), 1e-12f);
        float4* kp4 = (float4*)(khh + lane * KV_PITCH);
        float4* vp4 = (float4*)(vhh + lane * KV_PITCH);
        #pragma unroll
        for (int w = 0; w < 8; w++) {
            int d = w * 4;
            q[d] *= qf; q[d+1] *= qf; q[d+2] *= qf; q[d+3] *= qf;
            kp4[w] = make_float4(kv[d] * kf_, kv[d+1] * kf_, kv[d+2] * kf_, kv[d+3] * kf_);
            vp4[w] = make_float4(vv[d], vv[d+1], vv[d+2], vv[d+3]);
        }
    }
    __syncwarp();

    if (lane < SEQ) {
        float lg[SEQ];
        float mx = -1e30f;
        #pragma unroll
        for (int j = 0; j < SEQ; j++) {
            const float4* kp4 = (const float4*)(khh + j * KV_PITCH);
            float dot = 0.0f;
            #pragma unroll
            for (int tt = 0; tt < 8; tt++) {
                float4 kvv = kp4[tt];
                dot += q[tt * 4 + 0] * kvv.x + q[tt * 4 + 1] * kvv.y
                     + q[tt * 4 + 2] * kvv.z + q[tt * 4 + 3] * kvv.w;
            }
            lg[j] = dot;
            mx = fmaxf(mx, dot);
        }
        float ssum = 0.0f;
        #pragma unroll
        for (int j = 0; j < SEQ; j++) {
            lg[j] = expf(lg[j] - mx);
            ssum += lg[j];
        }
        float inv = 1.0f / ssum;

        float acc[32];
        #pragma unroll
        for (int d = 0; d < 32; d++) acc[d] = 0.0f;
        #pragma unroll
        for (int j = 0; j < SEQ; j++) {
            float a = lg[j];
            const float4* vp4 = (const float4*)(vhh + j * KV_PITCH);
            #pragma unroll
            for (int tt = 0; tt < 8; tt++) {
                float4 vvv = vp4[tt];
                acc[tt * 4 + 0] += a * vvv.x;
                acc[tt * 4 + 1] += a * vvv.y;
                acc[tt * 4 + 2] += a * vvv.z;
                acc[tt * 4 + 3] += a * vvv.w;
            }
        }
        union { int4 i4; __nv_bfloat162 h2[4]; } u;
        int4* op = (int4*)(g_attn + ((size_t)n * SEQ + lane) * DMODEL + h * HDIM);
        #pragma unroll
        for (int w = 0; w < 4; w++) {
            #pragma unroll
            for (int e = 0; e < 4; e++)
                u.h2[e] = __floats2bfloat162_rn(acc[w * 8 + 2 * e] * inv,
                                                acc[w * 8 + 2 * e + 1] * inv);
            op[w] = u.i4;
        }
    }
}

// ------------------------- launch -------------------------
extern "C" void kernel_launch(void* const* d_in, const int* in_sizes, int n_in,
                              void* d_out, int out_size) {
    const float* x           = (const float*)d_in[0];
    const float* ln1_g       = (const float*)d_in[1];
    const float* ln1_b       = (const float*)d_in[2];
    const float* qkv_w       = (const float*)d_in[3];
    const float* qkv_b       = (const float*)d_in[4];
    const float* proj_w      = (const float*)d_in[5];
    const float* proj_b      = (const float*)d_in[6];
    const float* logit_scale = (const float*)d_in[7];
    const float* ln2_g       = (const float*)d_in[8];
    const float* ln2_b       = (const float*)d_in[9];
    const float* w1          = (const float*)d_in[10];
    const float* b1          = (const float*)d_in[11];
    const float* w2          = (const float*)d_in[12];
    const float* b2          = (const float*)d_in[13];

    void *p_yb, *p_qkv, *p_attn, *p_x2, *p_y2, *p_hid, *p_wqkv, *p_wproj, *p_w1, *p_w2;
    cudaGetSymbolAddress(&p_yb, g_yb);
    cudaGetSymbolAddress(&p_qkv, g_qkv);
    cudaGetSymbolAddress(&p_attn, g_attn);
    cudaGetSymbolAddress(&p_x2, g_x2);
    cudaGetSymbolAddress(&p_y2, g_y2);
    cudaGetSymbolAddress(&p_hid, g_hid);
    cudaGetSymbolAddress(&p_wqkv, g_wqkv);
    cudaGetSymbolAddress(&p_wproj, g_wproj);
    cudaGetSymbolAddress(&p_w1, g_w1);
    cudaGetSymbolAddress(&p_w2, g_w2);

    cudaFuncSetAttribute(attn_kernel, cudaFuncAttributeMaxDynamicSharedMemorySize, ATTN_SMEM_BYTES);
    cudaFuncSetAttribute(mm_gemm<EPI_BF16>, cudaFuncAttributeMaxDynamicSharedMemorySize, GSMEM);
    cudaFuncSetAttribute(mm_gemm<EPI_PROJ>, cudaFuncAttributeMaxDynamicSharedMemorySize, GSMEM);
    cudaFuncSetAttribute(mm_gemm<EPI_GELU>, cudaFuncAttributeMaxDynamicSharedMemorySize, GSMEM);
    cudaFuncSetAttribute(mm_gemm<EPI_OUT>,  cudaFuncAttributeMaxDynamicSharedMemorySize, GSMEM);

    // 1) weights -> bf16, transposed to [N,K]
    convert_w_kernel<<<768, 256>>>(qkv_w, proj_w, w1, w2);
    // 2) LN1: x -> yb
    ln_kernel<<<NTOK / 8, 256>>>(x, ln1_g, ln1_b, (__nv_bfloat16*)p_yb);
    // 3) qkv GEMM: yb @ wqkv^T + b -> qkv (bf16)
    mm_gemm<EPI_BF16><<<dim3(D3 / 128, NTOK / 128), 256, GSMEM>>>(
        (const __nv_bfloat16*)p_yb, (const __nv_bfloat16*)p_wqkv, qkv_b, nullptr, p_qkv, D3, DMODEL);
    // 4) attention
    attn_kernel<<<NSEQ, 256, ATTN_SMEM_BYTES>>>(logit_scale);
    // 5) proj GEMM + residual -> x2 (fp32)
    mm_gemm<EPI_PROJ><<<dim3(DMODEL / 128, NTOK / 128), 256, GSMEM>>>(
        (const __nv_bfloat16*)p_attn, (const __nv_bfloat16*)p_wproj, proj_b, x, p_x2, DMODEL, DMODEL);
    // 6) LN2: x2 -> y2
    ln_kernel<<<NTOK / 8, 256>>>((const float*)p_x2, ln2_g, ln2_b, (__nv_bfloat16*)p_y2);
    // 7) ffn1 GEMM + gelu -> hid (bf16)
    mm_gemm<EPI_GELU><<<dim3(DFFN / 128, NTOK / 128), 256, GSMEM>>>(
        (const __nv_bfloat16*)p_y2, (const __nv_bfloat16*)p_w1, b1, nullptr, p_hid, DFFN, DMODEL);
    // 8) ffn2 GEMM + residual -> out (fp32)
    mm_gemm<EPI_OUT><<<dim3(DMODEL / 128, NTOK / 128), 256, GSMEM>>>(
        (const __nv_bfloat16*)p_hid, (const __nv_bfloat16*)p_w2, b2, (const float*)p_x2, d_out, DMODEL, DFFN);
}

// round 14
// speedup vs baseline: 2.2941x; 1.0612x over previous
#include <cuda_runtime.h>
#include <cuda_bf16.h>
#include <cstdint>
#include <math.h>

// Problem dims
#define NTOK   204800          // B*T*V = 64*128*25
#define NSEQ   8192            // B*T
#define SEQ    25
#define DMODEL 256
#define NHEAD  8
#define HDIM   32
#define DFFN   1024
#define D3     768

// ------------------------- scratch (device globals) -------------------------
__device__ __nv_bfloat16 g_yb  [(size_t)NTOK * DMODEL];   // LN1 output, bf16
__device__ __nv_bfloat16 g_qkv [(size_t)NTOK * D3];       // qkv, bf16
__device__ __nv_bfloat16 g_attn[(size_t)NTOK * DMODEL];   // attention out, bf16
__device__ float         g_x2  [(size_t)NTOK * DMODEL];   // residual after proj, fp32
__device__ __nv_bfloat16 g_y2  [(size_t)NTOK * DMODEL];   // LN2 output, bf16
__device__ __nv_bfloat16 g_hid [(size_t)NTOK * DFFN];     // ffn hidden, bf16
// weights stored TRANSPOSED: [N, K] K-major (B operand, row.col mma)
__device__ __nv_bfloat16 g_wqkv [D3   * DMODEL];
__device__ __nv_bfloat16 g_wproj[DMODEL * DMODEL];
__device__ __nv_bfloat16 g_w1   [DFFN * DMODEL];
__device__ __nv_bfloat16 g_w2   [DMODEL * DFFN];

// ------------------------- ptx helpers -------------------------
__device__ __forceinline__ void cp_async16(uint32_t smem_dst, const void* gmem_src) {
    asm volatile("cp.async.cg.shared.global [%0], [%1], 16;\n" :: "r"(smem_dst), "l"(gmem_src));
}
__device__ __forceinline__ void ldmatrix_x4(uint32_t& r0, uint32_t& r1, uint32_t& r2,
                                            uint32_t& r3, uint32_t addr) {
    asm volatile("ldmatrix.sync.aligned.m8n8.x4.shared.b16 {%0,%1,%2,%3}, [%4];"
                 : "=r"(r0), "=r"(r1), "=r"(r2), "=r"(r3) : "r"(addr));
}
__device__ __forceinline__ void mma16816(float& d0, float& d1, float& d2, float& d3,
                                         uint32_t a0, uint32_t a1, uint32_t a2, uint32_t a3,
                                         uint32_t b0, uint32_t b1) {
    asm volatile(
        "mma.sync.aligned.m16n8k16.row.col.f32.bf16.bf16.f32 "
        "{%0,%1,%2,%3}, {%4,%5,%6,%7}, {%8,%9}, {%0,%1,%2,%3};"
        : "+f"(d0), "+f"(d1), "+f"(d2), "+f"(d3)
        : "r"(a0), "r"(a1), "r"(a2), "r"(a3), "r"(b0), "r"(b1));
}

// ------------------------- weight fp32 -> bf16 (TRANSPOSED to [N,K]) -----------
__global__ void convert_w_kernel(const float* __restrict__ qkv_w,
                                 const float* __restrict__ proj_w,
                                 const float* __restrict__ w1,
                                 const float* __restrict__ w2) {
    int i0 = blockIdx.x * blockDim.x + threadIdx.x;
    int stride = gridDim.x * blockDim.x;
    for (int i = i0; i < D3 * DMODEL; i += stride) {
        int n = i >> 8, k = i & 255;
        g_wqkv[i] = __float2bfloat16(qkv_w[k * D3 + n]);
    }
    for (int i = i0; i < DMODEL * DMODEL; i += stride) {
        int n = i >> 8, k = i & 255;
        g_wproj[i] = __float2bfloat16(proj_w[k * DMODEL + n]);
    }
    for (int i = i0; i < DFFN * DMODEL; i += stride) {
        int n = i >> 8, k = i & 255;
        g_w1[i] = __float2bfloat16(w1[k * DFFN + n]);
    }
    for (int i = i0; i < DMODEL * DFFN; i += stride) {
        int n = i >> 10, k = i & 1023;
        g_w2[i] = __float2bfloat16(w2[k * DMODEL + n]);
    }
}

// ------------------------- LayerNorm (warp per row, D=256) -------------------------
__global__ __launch_bounds__(256) void ln_kernel(const float* __restrict__ X,
                                                 const float* __restrict__ gam,
                                                 const float* __restrict__ bet,
                                                 __nv_bfloat16* __restrict__ Y) {
    int warp = (blockIdx.x * blockDim.x + threadIdx.x) >> 5;
    int lane = threadIdx.x & 31;
    if (warp >= NTOK) return;
    const float4* xp = (const float4*)(X + (size_t)warp * DMODEL);
    float4 v0 = xp[lane * 2];
    float4 v1 = xp[lane * 2 + 1];
    float s = v0.x + v0.y + v0.z + v0.w + v1.x + v1.y + v1.z + v1.w;
    #pragma unroll
    for (int o = 16; o > 0; o >>= 1) s += __shfl_xor_sync(0xffffffffu, s, o);
    float m = s * (1.0f / 256.0f);
    float d0x = v0.x - m, d0y = v0.y - m, d0z = v0.z - m, d0w = v0.w - m;
    float d1x = v1.x - m, d1y = v1.y - m, d1z = v1.z - m, d1w = v1.w - m;
    float vs = d0x*d0x + d0y*d0y + d0z*d0z + d0w*d0w + d1x*d1x + d1y*d1y + d1z*d1z + d1w*d1w;
    #pragma unroll
    for (int o = 16; o > 0; o >>= 1) vs += __shfl_xor_sync(0xffffffffu, vs, o);
    float rstd = rsqrtf(vs * (1.0f / 256.0f) + 1e-5f);
    const float4* gp = (const float4*)gam;
    const float4* bp = (const float4*)bet;
    float4 g0 = gp[lane * 2], g1 = gp[lane * 2 + 1];
    float4 b0 = bp[lane * 2], b1 = bp[lane * 2 + 1];
    float y[8];
    y[0] = d0x * rstd * g0.x + b0.x;  y[1] = d0y * rstd * g0.y + b0.y;
    y[2] = d0z * rstd * g0.z + b0.z;  y[3] = d0w * rstd * g0.w + b0.w;
    y[4] = d1x * rstd * g1.x + b1.x;  y[5] = d1y * rstd * g1.y + b1.y;
    y[6] = d1z * rstd * g1.z + b1.z;  y[7] = d1w * rstd * g1.w + b1.w;
    union { int4 i4; __nv_bfloat162 h2[4]; } u;
    u.h2[0] = __floats2bfloat162_rn(y[0], y[1]);
    u.h2[1] = __floats2bfloat162_rn(y[2], y[3]);
    u.h2[2] = __floats2bfloat162_rn(y[4], y[5]);
    u.h2[3] = __floats2bfloat162_rn(y[6], y[7]);
    *((int4*)(Y + (size_t)warp * DMODEL + lane * 8)) = u.i4;
}

// ------------------------- mma.sync GEMM -------------------------
// C[M,N] = A[M,K] @ Bw[N,K]^T + bias (+ epilogue).
// 128x128 CTA tile, BK=32, 4-stage cp.async pipeline, ONE barrier per chunk.
// FOUR warps (128 threads), warp tile 64x64: 32 MMAs per k16 step against
// 8 ldmatrix.x4 -> 2x arithmetic per shared-load vs the 8-warp version.
enum { EPI_BF16 = 0, EPI_PROJ = 1, EPI_GELU = 2, EPI_OUT = 3 };

#define ROWB   80                    // padded row pitch in bytes (32 bf16 + 8 pad)
#define STAGE_A 10240                // 128 * 80
#define STAGE  20480                 // A + B per stage
#define NSTAGE 4
#define GSMEM  (NSTAGE * STAGE)      // 81920

template <int EPI>
__global__ __launch_bounds__(128) void mm_gemm(
    const __nv_bfloat16* __restrict__ A,
    const __nv_bfloat16* __restrict__ Bw,
    const float* __restrict__ bias,
    const float* __restrict__ res,
    void* __restrict__ out, int N, int K)
{
    extern __shared__ __align__(128) char smem[];
    const uint32_t sb = (uint32_t)__cvta_generic_to_shared(smem);
    const int t = threadIdx.x, wid = t >> 5, lane = t & 31;
    const int wm = wid & 1;          // 0..1 -> 64-row slab
    const int wn = wid >> 1;         // 0..1 -> 64-col slab
    const size_t m0 = (size_t)blockIdx.y * 128;
    const int n0 = blockIdx.x * 128;
    const int C = K >> 5;            // BK=32 chunks

    auto load_chunk = [&](int c, int s) {
        const uint32_t base = sb + (uint32_t)s * STAGE;
        const int k0 = c << 5;
        #pragma unroll
        for (int i = 0; i < 4; i++) {
            int idx = i * 128 + t;
            int r = idx >> 2, cc = idx & 3;
            cp_async16(base + (uint32_t)(r * ROWB + cc * 16),
                       A + (m0 + r) * K + k0 + cc * 8);
        }
        #pragma unroll
        for (int i = 0; i < 4; i++) {
            int idx = i * 128 + t;
            int r = idx >> 2, cc = idx & 3;
            cp_async16(base + STAGE_A + (uint32_t)(r * ROWB + cc * 16),
                       Bw + (size_t)(n0 + r) * K + k0 + cc * 8);
        }
        asm volatile("cp.async.commit_group;");
    };

    float acc[4][8][4];
    #pragma unroll
    for (int i = 0; i < 4; i++)
        #pragma unroll
        for (int j = 0; j < 8; j++)
            #pragma unroll
            for (int e = 0; e < 4; e++) acc[i][j][e] = 0.0f;

    // prefetch first 3 stages
    load_chunk(0, 0);
    if (C > 1) load_chunk(1, 1);
    if (C > 2) load_chunk(2, 2);

    // ldmatrix lane roles for B
    const int b_g = lane >> 3;
    const int b_row = lane & 7;
    const int b_noff = (b_g >> 1) * 8 + b_row;
    const int b_kc16 = (b_g & 1) * 16;

    for (int c = 0; c < C; c++) {
        if (c < C - 2)      { asm volatile("cp.async.wait_group 2;"); }
        else if (c == C - 2){ asm volatile("cp.async.wait_group 1;"); }
        else                { asm volatile("cp.async.wait_group 0;"); }
        __syncthreads();
        // safe: stage (c+3)%4 == (c-1)%4 fully consumed before this barrier.
        if (c + 3 < C) load_chunk(c + 3, (c + 3) & 3);

        const uint32_t aBase = sb + (uint32_t)(c & 3) * STAGE;
        const uint32_t bBase = aBase + STAGE_A;

        #pragma unroll
        for (int ks = 0; ks < 2; ks++) {
            uint32_t a[4][4];
            #pragma unroll
            for (int i = 0; i < 4; i++) {
                uint32_t addr = aBase
                    + (uint32_t)((wm * 64 + i * 16 + (lane & 15)) * ROWB
                                 + ks * 32 + (lane >> 4) * 16);
                ldmatrix_x4(a[i][0], a[i][1], a[i][2], a[i][3], addr);
            }
            uint32_t bb[8][2];
            #pragma unroll
            for (int g4 = 0; g4 < 4; g4++) {
                int nrow = wn * 64 + g4 * 16 + b_noff;
                uint32_t addr = bBase + (uint32_t)(nrow * ROWB + ks * 32 + b_kc16);
                ldmatrix_x4(bb[g4 * 2][0], bb[g4 * 2][1],
                            bb[g4 * 2 + 1][0], bb[g4 * 2 + 1][1], addr);
            }
            #pragma unroll
            for (int j = 0; j < 8; j++)
                #pragma unroll
                for (int i = 0; i < 4; i++)
                    mma16816(acc[i][j][0], acc[i][j][1], acc[i][j][2], acc[i][j][3],
                             a[i][0], a[i][1], a[i][2], a[i][3], bb[j][0], bb[j][1]);
        }
    }

    // epilogue straight from fragments
    const int qrow = lane >> 2;
    const int qcol = (lane & 3) * 2;
    #pragma unroll
    for (int i = 0; i < 4; i++) {
        #pragma unroll
        for (int j = 0; j < 8; j++) {
            int col = n0 + wn * 64 + j * 8 + qcol;
            float2 bb = *(const float2*)(bias + col);
            #pragma unroll
            for (int h = 0; h < 2; h++) {
                size_t row = m0 + wm * 64 + i * 16 + qrow + h * 8;
                float v0 = acc[i][j][2 * h + 0] + bb.x;
                float v1 = acc[i][j][2 * h + 1] + bb.y;
                size_t o = row * (size_t)N + col;
                if (EPI == EPI_BF16) {
                    *(__nv_bfloat162*)((__nv_bfloat16*)out + o) = __floats2bfloat162_rn(v0, v1);
                } else if (EPI == EPI_GELU) {
                    v0 = 0.5f * v0 * (1.0f + erff(v0 * 0.70710678118654752f));
                    v1 = 0.5f * v1 * (1.0f + erff(v1 * 0.70710678118654752f));
                    *(__nv_bfloat162*)((__nv_bfloat16*)out + o) = __floats2bfloat162_rn(v0, v1);
                } else {
                    float2 rr = *(const float2*)(res + o);
                    float2 ov = make_float2(v0 + rr.x, v1 + rr.y);
                    *(float2*)((float*)out + o) = ov;
                }
            }
        }
    }
}

// ------------------------- Cosine attention -------------------------
// Block per sequence, warp per head. qkv tile staged through smem with
// coalesced loads; per-lane reads are conflict-free LDS.32 (pitch 385 words).
// k/v float arrays padded to pitch 36 -> conflict-free STS.128 / LDS broadcast.
#define STG_PITCH 385                 // uint32 words per staged row (384 + 1 pad)
#define KV_PITCH  36                  // floats per k/v row (32 + 4 pad)
#define KV_HEAD   (SEQ * KV_PITCH)    // 900 floats per head
#define ATTN_SMEM_WORDS (9632 + 2 * NHEAD * KV_HEAD)   // 9632 + 14400 = 24032
#define ATTN_SMEM_BYTES (ATTN_SMEM_WORDS * 4)          // 96128 B

__global__ __launch_bounds__(256) void attn_kernel(const float* __restrict__ logit_scale) {
    extern __shared__ float sm[];
    uint32_t* stage = (uint32_t*)sm;             // [25][385] words (bf16x2)
    float* kf = sm + 9632;                        // [8][25][36]
    float* vf = kf + NHEAD * KV_HEAD;             // [8][25][36]

    const int n = blockIdx.x;
    const int t = threadIdx.x;
    const int h = t >> 5;
    const int lane = t & 31;

    // ---- coalesced stage of the 25x768 bf16 qkv tile (2400 int4) ----
    {
        const int4* gq = (const int4*)(g_qkv + (size_t)n * SEQ * D3);
        #pragma unroll
        for (int i = 0; i < 10; i++) {
            int idx = i * 256 + t;
            if (idx < 2400) {
                int r = idx / 96, c = idx % 96;        // c in int4 units
                int4 v4 = gq[r * 96 + c];
                uint32_t* d = stage + r * STG_PITCH + c * 4;
                d[0] = ((const uint32_t*)&v4)[0];
                d[1] = ((const uint32_t*)&v4)[1];
                d[2] = ((const uint32_t*)&v4)[2];
                d[3] = ((const uint32_t*)&v4)[3];
            }
        }
    }
    __syncthreads();

    float scale = expf(fminf(logit_scale[h], 4.6051701859880914f));  // log(100)
    float* khh = kf + h * KV_HEAD;
    float* vhh = vf + h * KV_HEAD;

    float q[32];
    if (lane < SEQ) {
        const uint32_t* row = stage + lane * STG_PITCH + h * 16;
        float kv[32], vv[32];
        float qs = 0.0f, ks = 0.0f;
        #pragma unroll
        for (int c = 0; c < 16; c++) {
            float2 fq = __bfloat1622float2(*(const __nv_bfloat162*)&row[c]);
            float2 fk = __bfloat1622float2(*(const __nv_bfloat162*)&row[c + 128]);
            float2 fv = __bfloat1622float2(*(const __nv_bfloat162*)&row[c + 256]);
            int d = c * 2;
            q[d] = fq.x;   q[d + 1] = fq.y;
            kv[d] = fk.x;  kv[d + 1] = fk.y;
            vv[d] = fv.x;  vv[d + 1] = fv.y;
            qs += fq.x * fq.x + fq.y * fq.y;
            ks += fk.x * fk.x + fk.y * fk.y;
        }
        float qf = scale * 0.17677669529663687f / fmaxf(sqrtf(qs), 1e-12f);  // * 1/sqrt(32)
        float kf_ = 1.0f / fmaxf(sqrtf(ks), 1e-12f);
        float4* kp4 = (float4*)(khh + lane * KV_PITCH);
        float4* vp4 = (float4*)(vhh + lane * KV_PITCH);
        #pragma unroll
        for (int w = 0; w < 8; w++) {
            int d = w * 4;
            q[d] *= qf; q[d+1] *= qf; q[d+2] *= qf; q[d+3] *= qf;
            kp4[w] = make_float4(kv[d] * kf_, kv[d+1] * kf_, kv[d+2] * kf_, kv[d+3] * kf_);
            vp4[w] = make_float4(vv[d], vv[d+1], vv[d+2], vv[d+3]);
        }
    }
    __syncwarp();

    if (lane < SEQ) {
        float lg[SEQ];
        float mx = -1e30f;
        #pragma unroll
        for (int j = 0; j < SEQ; j++) {
            const float4* kp4 = (const float4*)(khh + j * KV_PITCH);
            float dot = 0.0f;
            #pragma unroll
            for (int tt = 0; tt < 8; tt++) {
                float4 kvv = kp4[tt];
                dot += q[tt * 4 + 0] * kvv.x + q[tt * 4 + 1] * kvv.y
                     + q[tt * 4 + 2] * kvv.z + q[tt * 4 + 3] * kvv.w;
            }
            lg[j] = dot;
            mx = fmaxf(mx, dot);
        }
        float ssum = 0.0f;
        #pragma unroll
        for (int j = 0; j < SEQ; j++) {
            lg[j] = expf(lg[j] - mx);
            ssum += lg[j];
        }
        float inv = 1.0f / ssum;

        float acc[32];
        #pragma unroll
        for (int d = 0; d < 32; d++) acc[d] = 0.0f;
        #pragma unroll
        for (int j = 0; j < SEQ; j++) {
            float a = lg[j];
            const float4* vp4 = (const float4*)(vhh + j * KV_PITCH);
            #pragma unroll
            for (int tt = 0; tt < 8; tt++) {
                float4 vvv = vp4[tt];
                acc[tt * 4 + 0] += a * vvv.x;
                acc[tt * 4 + 1] += a * vvv.y;
                acc[tt * 4 + 2] += a * vvv.z;
                acc[tt * 4 + 3] += a * vvv.w;
            }
        }
        union { int4 i4; __nv_bfloat162 h2[4]; } u;
        int4* op = (int4*)(g_attn + ((size_t)n * SEQ + lane) * DMODEL + h * HDIM);
        #pragma unroll
        for (int w = 0; w < 4; w++) {
            #pragma unroll
            for (int e = 0; e < 4; e++)
                u.h2[e] = __floats2bfloat162_rn(acc[w * 8 + 2 * e] * inv,
                                                acc[w * 8 + 2 * e + 1] * inv);
            op[w] = u.i4;
        }
    }
}

// ------------------------- launch -------------------------
extern "C" void kernel_launch(void* const* d_in, const int* in_sizes, int n_in,
                              void* d_out, int out_size) {
    const float* x           = (const float*)d_in[0];
    const float* ln1_g       = (const float*)d_in[1];
    const float* ln1_b       = (const float*)d_in[2];
    const float* qkv_w       = (const float*)d_in[3];
    const float* qkv_b       = (const float*)d_in[4];
    const float* proj_w      = (const float*)d_in[5];
    const float* proj_b      = (const float*)d_in[6];
    const float* logit_scale = (const float*)d_in[7];
    const float* ln2_g       = (const float*)d_in[8];
    const float* ln2_b       = (const float*)d_in[9];
    const float* w1          = (const float*)d_in[10];
    const float* b1          = (const float*)d_in[11];
    const float* w2          = (const float*)d_in[12];
    const float* b2          = (const float*)d_in[13];

    void *p_yb, *p_qkv, *p_attn, *p_x2, *p_y2, *p_hid, *p_wqkv, *p_wproj, *p_w1, *p_w2;
    cudaGetSymbolAddress(&p_yb, g_yb);
    cudaGetSymbolAddress(&p_qkv, g_qkv);
    cudaGetSymbolAddress(&p_attn, g_attn);
    cudaGetSymbolAddress(&p_x2, g_x2);
    cudaGetSymbolAddress(&p_y2, g_y2);
    cudaGetSymbolAddress(&p_hid, g_hid);
    cudaGetSymbolAddress(&p_wqkv, g_wqkv);
    cudaGetSymbolAddress(&p_wproj, g_wproj);
    cudaGetSymbolAddress(&p_w1, g_w1);
    cudaGetSymbolAddress(&p_w2, g_w2);

    cudaFuncSetAttribute(attn_kernel, cudaFuncAttributeMaxDynamicSharedMemorySize, ATTN_SMEM_BYTES);
    cudaFuncSetAttribute(mm_gemm<EPI_BF16>, cudaFuncAttributeMaxDynamicSharedMemorySize, GSMEM);
    cudaFuncSetAttribute(mm_gemm<EPI_PROJ>, cudaFuncAttributeMaxDynamicSharedMemorySize, GSMEM);
    cudaFuncSetAttribute(mm_gemm<EPI_GELU>, cudaFuncAttributeMaxDynamicSharedMemorySize, GSMEM);
    cudaFuncSetAttribute(mm_gemm<EPI_OUT>,  cudaFuncAttributeMaxDynamicSharedMemorySize, GSMEM);

    // 1) weights -> bf16, transposed to [N,K]
    convert_w_kernel<<<768, 256>>>(qkv_w, proj_w, w1, w2);
    // 2) LN1: x -> yb
    ln_kernel<<<NTOK / 8, 256>>>(x, ln1_g, ln1_b, (__nv_bfloat16*)p_yb);
    // 3) qkv GEMM: yb @ wqkv^T + b -> qkv (bf16)
    mm_gemm<EPI_BF16><<<dim3(D3 / 128, NTOK / 128), 128, GSMEM>>>(
        (const __nv_bfloat16*)p_yb, (const __nv_bfloat16*)p_wqkv, qkv_b, nullptr, p_qkv, D3, DMODEL);
    // 4) attention
    attn_kernel<<<NSEQ, 256, ATTN_SMEM_BYTES>>>(logit_scale);
    // 5) proj GEMM + residual -> x2 (fp32)
    mm_gemm<EPI_PROJ><<<dim3(DMODEL / 128, NTOK / 128), 128, GSMEM>>>(
        (const __nv_bfloat16*)p_attn, (const __nv_bfloat16*)p_wproj, proj_b, x, p_x2, DMODEL, DMODEL);
    // 6) LN2: x2 -> y2
    ln_kernel<<<NTOK / 8, 256>>>((const float*)p_x2, ln2_g, ln2_b, (__nv_bfloat16*)p_y2);
    // 7) ffn1 GEMM + gelu -> hid (bf16)
    mm_gemm<EPI_GELU><<<dim3(DFFN / 128, NTOK / 128), 128, GSMEM>>>(
        (const __nv_bfloat16*)p_y2, (const __nv_bfloat16*)p_w1, b1, nullptr, p_hid, DFFN, DMODEL);
    // 8) ffn2 GEMM + residual -> out (fp32)
    mm_gemm<EPI_OUT><<<dim3(DMODEL / 128, NTOK / 128), 128, GSMEM>>>(
        (const __nv_bfloat16*)p_hid, (const __nv_bfloat16*)p_w2, b2, (const float*)p_x2, d_out, DMODEL, DFFN);
}